// round 1
// baseline (speedup 1.0000x reference)
#include <cuda_runtime.h>
#include <math.h>
#include <stdint.h>

#define BB 2
#define SS 2048
#define DD 2048
#define HH 16
#define KVH 4
#define HD 128
#define MM (BB*SS)        // 4096 rows
#define KVD (KVH*HD)      // 512

// ---------------- scratch (device globals; no allocation allowed) ----------
__device__ float g_Qp[(size_t)MM*DD];    // x @ wq^T            [b,s,h,d]
__device__ float g_Kp[(size_t)MM*KVD];   // x @ wk^T            [b,s,kh,d]
__device__ float g_Vp[(size_t)MM*KVD];   // x @ wv^T            [b,s,kh,d]
__device__ float g_Qt[(size_t)MM*DD];    // roped, transposed   [b,h,s,d]
__device__ float g_Kt[(size_t)MM*KVD];   // roped, transposed   [b,kh,s,d]
__device__ float g_Vt[(size_t)MM*KVD];   // transposed          [b,kh,s,d]
__device__ float g_AttO[(size_t)MM*DD];  // attention out       [b,s,h*d]

// ---------------- tf32 helpers ---------------------------------------------
__device__ __forceinline__ uint32_t f2tf(float x){
    uint32_t u; asm("cvt.rna.tf32.f32 %0, %1;" : "=r"(u) : "f"(x)); return u;
}
__device__ __forceinline__ void mma8(float* c, const uint32_t* a, const uint32_t* b){
    asm volatile("mma.sync.aligned.m16n8k8.row.col.f32.tf32.tf32.f32 "
        "{%0,%1,%2,%3}, {%4,%5,%6,%7}, {%8,%9}, {%0,%1,%2,%3};"
        : "+f"(c[0]),"+f"(c[1]),"+f"(c[2]),"+f"(c[3])
        : "r"(a[0]),"r"(a[1]),"r"(a[2]),"r"(a[3]),"r"(b[0]),"r"(b[1]));
}

// ---------------- GEMM: C[M,N] = A[M,K] @ W[N,K]^T (tf32 accum fp32) -------
// block tile 128x128, K-step 32, 8 warps (2m x 4n), warp tile 64x32
__global__ void __launch_bounds__(256) gemm_tf32(const float* __restrict__ A,
                                                 const float* __restrict__ W,
                                                 float* __restrict__ C,
                                                 int N, int K)
{
    __shared__ uint32_t As[32][132];   // [k][m], +4 pad -> conflict-free frags
    __shared__ uint32_t Bs[32][132];   // [k][n]
    const int tid  = threadIdx.x;
    const int warp = tid >> 5, lane = tid & 31;
    const int g = lane >> 2, t = lane & 3;
    const int wm = warp & 1, wn = warp >> 1;
    const int m0 = blockIdx.y * 128, n0 = blockIdx.x * 128;

    float acc[4][4][4];
    #pragma unroll
    for (int a=0;a<4;a++)
        #pragma unroll
        for (int b2=0;b2<4;b2++)
            #pragma unroll
            for (int c=0;c<4;c++) acc[a][b2][c]=0.f;

    for (int kt = 0; kt < K; kt += 32) {
        #pragma unroll
        for (int i = 0; i < 4; i++) {
            int idx = tid + i*256;          // 0..1023
            int row = idx >> 3;             // 0..127
            int kc  = (idx & 7) << 2;       // 0,4,..,28
            float4 va = *(const float4*)(A + (size_t)(m0+row)*K + kt + kc);
            As[kc+0][row]=f2tf(va.x); As[kc+1][row]=f2tf(va.y);
            As[kc+2][row]=f2tf(va.z); As[kc+3][row]=f2tf(va.w);
            float4 vb = *(const float4*)(W + (size_t)(n0+row)*K + kt + kc);
            Bs[kc+0][row]=f2tf(vb.x); Bs[kc+1][row]=f2tf(vb.y);
            Bs[kc+2][row]=f2tf(vb.z); Bs[kc+3][row]=f2tf(vb.w);
        }
        __syncthreads();
        #pragma unroll
        for (int kk = 0; kk < 32; kk += 8) {
            uint32_t af[4][4], bf[4][2];
            #pragma unroll
            for (int mi=0; mi<4; mi++){
                int r = wm*64 + mi*16 + g;
                af[mi][0] = As[kk+t  ][r];
                af[mi][1] = As[kk+t  ][r+8];
                af[mi][2] = As[kk+t+4][r];
                af[mi][3] = As[kk+t+4][r+8];
            }
            #pragma unroll
            for (int ni=0; ni<4; ni++){
                int c = wn*32 + ni*8 + g;
                bf[ni][0] = Bs[kk+t  ][c];
                bf[ni][1] = Bs[kk+t+4][c];
            }
            #pragma unroll
            for (int mi=0; mi<4; mi++)
                #pragma unroll
                for (int ni=0; ni<4; ni++)
                    mma8(acc[mi][ni], af[mi], bf[ni]);
        }
        __syncthreads();
    }
    #pragma unroll
    for (int mi=0; mi<4; mi++){
        int r = m0 + wm*64 + mi*16 + g;
        #pragma unroll
        for (int ni=0; ni<4; ni++){
            int c = n0 + wn*32 + ni*8 + 2*t;
            *(float2*)(C + (size_t)r*N + c)     = make_float2(acc[mi][ni][0], acc[mi][ni][1]);
            *(float2*)(C + (size_t)(r+8)*N + c) = make_float2(acc[mi][ni][2], acc[mi][ni][3]);
        }
    }
}

// ---------------- RoPE + transposes ----------------------------------------
__global__ void rope_q_kernel(const float* __restrict__ cs, const float* __restrict__ sn){
    int idx = blockIdx.x*256 + threadIdx.x;     // MM*HH*64 pairs
    int i  = idx & 63;
    int h  = (idx >> 6) & (HH-1);
    int bs = idx >> 10;
    int s  = bs & (SS-1);
    int b  = bs >> 11;
    const float* src = g_Qp + ((size_t)bs*HH + h)*HD + 2*i;
    float xr = src[0], xi = src[1];
    float c = cs[s*64+i], si = sn[s*64+i];
    float* dst = g_Qt + (((size_t)(b*HH+h)*SS + s)*HD) + 2*i;
    dst[0] = xr*c - xi*si;
    dst[1] = xr*si + xi*c;
}
__global__ void rope_k_kernel(const float* __restrict__ cs, const float* __restrict__ sn){
    int idx = blockIdx.x*256 + threadIdx.x;     // MM*KVH*64 pairs
    int i  = idx & 63;
    int h  = (idx >> 6) & (KVH-1);
    int bs = idx >> 8;
    int s  = bs & (SS-1);
    int b  = bs >> 11;
    const float* src = g_Kp + ((size_t)bs*KVH + h)*HD + 2*i;
    float xr = src[0], xi = src[1];
    float c = cs[s*64+i], si = sn[s*64+i];
    float* dst = g_Kt + (((size_t)(b*KVH+h)*SS + s)*HD) + 2*i;
    dst[0] = xr*c - xi*si;
    dst[1] = xr*si + xi*c;
}
__global__ void vtrans_kernel(){
    int idx = blockIdx.x*256 + threadIdx.x;     // MM*KVD/4 float4s
    int d4 = idx & 31;
    int h  = (idx >> 5) & (KVH-1);
    int bs = idx >> 7;
    int s  = bs & (SS-1);
    int b  = bs >> 11;
    float4 v = *(const float4*)(g_Vp + (size_t)idx*4);
    *(float4*)(g_Vt + (((size_t)(b*KVH+h)*SS + s)*HD) + d4*4) = v;
}

// ---------------- flash attention (fp32 SIMT, causal) ----------------------
// grid: (32 q-tiles, B*H=32); block 256 thr = 16(tx=cols/d) x 16(ty=rows)
#define FLASH_SMEM ((64*132 + 64*128 + 64*128 + 64*68)*4)

__global__ void __launch_bounds__(256) flash_kernel(){
    extern __shared__ float smf[];
    float* Qs = smf;              // [64][132]  (pad: rows 4 apart hit diff banks)
    float* Ks = smf + 64*132;     // [64][128]  XOR-swizzled d-chunks
    float* Vs = Ks  + 64*128;     // [64][128]
    float* Ps = Vs  + 64*128;     // [64][68]

    const int qt = blockIdx.x;
    const int bh = blockIdx.y;
    const int b = bh >> 4, h = bh & 15;
    const int kvh = h >> 2;
    const int q0 = qt * 64;
    const int tid = threadIdx.x;
    const int tx = tid & 15, ty = tid >> 4;

    const float* Qg = g_Qt + (size_t)(b*HH + h)   * SS * HD;
    const float* Kg = g_Kt + (size_t)(b*KVH + kvh)* SS * HD;
    const float* Vg = g_Vt + (size_t)(b*KVH + kvh)* SS * HD;

    for (int i = tid; i < 64*32; i += 256) {
        int row = i >> 5, dc = i & 31;
        *(float4*)(Qs + row*132 + dc*4) =
            *(const float4*)(Qg + (size_t)(q0+row)*HD + dc*4);
    }

    float m_r[4], l_r[4], O[4][8];
    #pragma unroll
    for (int i=0;i<4;i++){
        m_r[i] = -INFINITY; l_r[i] = 0.f;
        #pragma unroll
        for (int j=0;j<8;j++) O[i][j]=0.f;
    }
    const float scale = 0.08838834764831845f;  // 1/sqrt(128)

    for (int kti = 0; kti <= qt; kti++) {
        int k0 = kti * 64;
        __syncthreads();                      // Ps/Ks/Vs consumers done
        for (int i = tid; i < 64*32; i += 256) {
            int row = i >> 5, dc = i & 31;
            int pc = dc ^ ((row >> 2) & 7);   // swizzle: conflict-free K reads
            *(float4*)(Ks + row*128 + pc*4) =
                *(const float4*)(Kg + (size_t)(k0+row)*HD + dc*4);
            *(float4*)(Vs + row*128 + dc*4) =
                *(const float4*)(Vg + (size_t)(k0+row)*HD + dc*4);
        }
        __syncthreads();

        float acc[4][4];
        #pragma unroll
        for (int i=0;i<4;i++)
            #pragma unroll
            for(int j=0;j<4;j++) acc[i][j]=0.f;

        #pragma unroll 4
        for (int dc = 0; dc < 32; dc++) {
            float4 qv[4], kv[4];
            #pragma unroll
            for (int i=0;i<4;i++)
                qv[i] = *(const float4*)(Qs + (ty*4+i)*132 + dc*4);
            int pc = (dc ^ (tx & 7)) * 4;
            #pragma unroll
            for (int j=0;j<4;j++)
                kv[j] = *(const float4*)(Ks + (tx*4+j)*128 + pc);
            #pragma unroll
            for (int i=0;i<4;i++)
                #pragma unroll
                for (int j=0;j<4;j++)
                    acc[i][j] += qv[i].x*kv[j].x + qv[i].y*kv[j].y
                               + qv[i].z*kv[j].z + qv[i].w*kv[j].w;
        }

        const bool diag = (kti == qt);
        #pragma unroll
        for (int i=0;i<4;i++){
            int qi = q0 + ty*4 + i;
            float mt = -INFINITY;
            #pragma unroll
            for (int j=0;j<4;j++){
                float s = acc[i][j]*scale;
                if (diag && (k0 + tx*4 + j > qi)) s = -INFINITY;
                acc[i][j] = s;
                mt = fmaxf(mt, s);
            }
            #pragma unroll
            for (int o=8;o>=1;o>>=1)
                mt = fmaxf(mt, __shfl_xor_sync(0xffffffffu, mt, o));
            float mn  = fmaxf(m_r[i], mt);
            float fac = __expf(m_r[i] - mn);
            float sum = 0.f;
            #pragma unroll
            for (int j=0;j<4;j++){
                float p = __expf(acc[i][j] - mn);
                acc[i][j] = p;
                sum += p;
            }
            #pragma unroll
            for (int o=8;o>=1;o>>=1)
                sum += __shfl_xor_sync(0xffffffffu, sum, o);
            l_r[i] = l_r[i]*fac + sum;
            m_r[i] = mn;
            #pragma unroll
            for (int j=0;j<8;j++) O[i][j] *= fac;
            #pragma unroll
            for (int j=0;j<4;j++)
                Ps[(ty*4+i)*68 + tx*4 + j] = acc[i][j];
        }
        __syncthreads();

        #pragma unroll 2
        for (int k=0;k<64;k++){
            float pk[4];
            #pragma unroll
            for (int i=0;i<4;i++) pk[i] = Ps[(ty*4+i)*68 + k];
            float4 v0 = *(const float4*)(Vs + k*128 + tx*8);
            float4 v1 = *(const float4*)(Vs + k*128 + tx*8 + 4);
            #pragma unroll
            for (int i=0;i<4;i++){
                O[i][0] += pk[i]*v0.x; O[i][1] += pk[i]*v0.y;
                O[i][2] += pk[i]*v0.z; O[i][3] += pk[i]*v0.w;
                O[i][4] += pk[i]*v1.x; O[i][5] += pk[i]*v1.y;
                O[i][6] += pk[i]*v1.z; O[i][7] += pk[i]*v1.w;
            }
        }
    }

    #pragma unroll
    for (int i=0;i<4;i++){
        float inv = 1.f / l_r[i];
        int q = q0 + ty*4 + i;
        float* dst = g_AttO + ((size_t)(b*SS) + q)*DD + h*HD + tx*8;
        *(float4*)dst     = make_float4(O[i][0]*inv, O[i][1]*inv, O[i][2]*inv, O[i][3]*inv);
        *(float4*)(dst+4) = make_float4(O[i][4]*inv, O[i][5]*inv, O[i][6]*inv, O[i][7]*inv);
    }
}

// ---------------- launch ----------------------------------------------------
extern "C" void kernel_launch(void* const* d_in, const int* in_sizes, int n_in,
                              void* d_out, int out_size){
    const float* x  = (const float*)d_in[0];
    const float* fc = (const float*)d_in[1];
    const float* fs = (const float*)d_in[2];
    const float* wq = (const float*)d_in[3];
    const float* wk = (const float*)d_in[4];
    const float* wv = (const float*)d_in[5];
    const float* wo = (const float*)d_in[6];
    float* out = (float*)d_out;

    float *pQp, *pKp, *pVp, *pAo;
    cudaGetSymbolAddress((void**)&pQp, g_Qp);
    cudaGetSymbolAddress((void**)&pKp, g_Kp);
    cudaGetSymbolAddress((void**)&pVp, g_Vp);
    cudaGetSymbolAddress((void**)&pAo, g_AttO);

    cudaFuncSetAttribute(flash_kernel,
        cudaFuncAttributeMaxDynamicSharedMemorySize, FLASH_SMEM);

    gemm_tf32<<<dim3(16,32),256>>>(x, wq, pQp, 2048, 2048);
    gemm_tf32<<<dim3( 4,32),256>>>(x, wk, pKp,  512, 2048);
    gemm_tf32<<<dim3( 4,32),256>>>(x, wv, pVp,  512, 2048);
    rope_q_kernel<<<(MM*HH*64)/256, 256>>>(fc, fs);
    rope_k_kernel<<<(MM*KVH*64)/256, 256>>>(fc, fs);
    vtrans_kernel<<<(MM*KVD/4)/256, 256>>>();
    flash_kernel<<<dim3(32,32),256,FLASH_SMEM>>>();
    gemm_tf32<<<dim3(16,32),256>>>(pAo, wo, out, 2048, 2048);
}

// round 5
// speedup vs baseline: 1.0287x; 1.0287x over previous
#include <cuda_runtime.h>
#include <math.h>
#include <stdint.h>

#define BB 2
#define SS 2048
#define DD 2048
#define HH 16
#define KVH 4
#define HD 128
#define MM (BB*SS)        // 4096 rows
#define KVD (KVH*HD)      // 512

// ---------------- scratch (device globals; no allocation allowed) ----------
__device__ float g_Qp[(size_t)MM*DD];    // x @ wq^T            [b,s,h,d]
__device__ float g_Kp[(size_t)MM*KVD];   // x @ wk^T            [b,s,kh,d]
__device__ float g_Vp[(size_t)MM*KVD];   // x @ wv^T            [b,s,kh,d]
__device__ float g_Qt[(size_t)MM*DD];    // roped, transposed   [b,h,s,d]
__device__ float g_Kt[(size_t)MM*KVD];   // roped, transposed   [b,kh,s,d]
__device__ float g_Vt[(size_t)MM*KVD];   // transposed          [b,kh,s,d]
__device__ float g_AttO[(size_t)MM*DD];  // attention out       [b,s,h*d]

// ---------------- tf32 helpers ---------------------------------------------
__device__ __forceinline__ uint32_t f2tf(float x){
    uint32_t u; asm("cvt.rna.tf32.f32 %0, %1;" : "=r"(u) : "f"(x)); return u;
}
__device__ __forceinline__ void mma8(float* c, const uint32_t* a, const uint32_t* b){
    asm volatile("mma.sync.aligned.m16n8k8.row.col.f32.tf32.tf32.f32 "
        "{%0,%1,%2,%3}, {%4,%5,%6,%7}, {%8,%9}, {%0,%1,%2,%3};"
        : "+f"(c[0]),"+f"(c[1]),"+f"(c[2]),"+f"(c[3])
        : "r"(a[0]),"r"(a[1]),"r"(a[2]),"r"(a[3]),"r"(b[0]),"r"(b[1]));
}

// ---------------- GEMM: C[M,N] = A[M,K] @ W[N,K]^T (tf32 accum fp32) -------
// block tile 128x128, K-step 32, 8 warps (2m x 4n), warp tile 64x32
__global__ void __launch_bounds__(256) gemm_tf32(const float* __restrict__ A,
                                                 const float* __restrict__ W,
                                                 float* __restrict__ C,
                                                 int N, int K)
{
    __shared__ uint32_t As[32][132];   // [k][m], +4 pad -> conflict-free frags
    __shared__ uint32_t Bs[32][132];   // [k][n]
    const int tid  = threadIdx.x;
    const int warp = tid >> 5, lane = tid & 31;
    const int g = lane >> 2, t = lane & 3;
    const int wm = warp & 1, wn = warp >> 1;
    const int m0 = blockIdx.y * 128, n0 = blockIdx.x * 128;

    float acc[4][4][4];
    #pragma unroll
    for (int a=0;a<4;a++)
        #pragma unroll
        for (int b2=0;b2<4;b2++)
            #pragma unroll
            for (int c=0;c<4;c++) acc[a][b2][c]=0.f;

    for (int kt = 0; kt < K; kt += 32) {
        #pragma unroll
        for (int i = 0; i < 4; i++) {
            int idx = tid + i*256;          // 0..1023
            int row = idx >> 3;             // 0..127
            int kc  = (idx & 7) << 2;       // 0,4,..,28
            float4 va = *(const float4*)(A + (size_t)(m0+row)*K + kt + kc);
            As[kc+0][row]=f2tf(va.x); As[kc+1][row]=f2tf(va.y);
            As[kc+2][row]=f2tf(va.z); As[kc+3][row]=f2tf(va.w);
            float4 vb = *(const float4*)(W + (size_t)(n0+row)*K + kt + kc);
            Bs[kc+0][row]=f2tf(vb.x); Bs[kc+1][row]=f2tf(vb.y);
            Bs[kc+2][row]=f2tf(vb.z); Bs[kc+3][row]=f2tf(vb.w);
        }
        __syncthreads();
        #pragma unroll
        for (int kk = 0; kk < 32; kk += 8) {
            uint32_t af[4][4], bf[4][2];
            #pragma unroll
            for (int mi=0; mi<4; mi++){
                int r = wm*64 + mi*16 + g;
                af[mi][0] = As[kk+t  ][r];
                af[mi][1] = As[kk+t  ][r+8];
                af[mi][2] = As[kk+t+4][r];
                af[mi][3] = As[kk+t+4][r+8];
            }
            #pragma unroll
            for (int ni=0; ni<4; ni++){
                int c = wn*32 + ni*8 + g;
                bf[ni][0] = Bs[kk+t  ][c];
                bf[ni][1] = Bs[kk+t+4][c];
            }
            #pragma unroll
            for (int mi=0; mi<4; mi++)
                #pragma unroll
                for (int ni=0; ni<4; ni++)
                    mma8(acc[mi][ni], af[mi], bf[ni]);
        }
        __syncthreads();
    }
    #pragma unroll
    for (int mi=0; mi<4; mi++){
        int r = m0 + wm*64 + mi*16 + g;
        #pragma unroll
        for (int ni=0; ni<4; ni++){
            int c = n0 + wn*32 + ni*8 + 2*t;
            *(float2*)(C + (size_t)r*N + c)     = make_float2(acc[mi][ni][0], acc[mi][ni][1]);
            *(float2*)(C + (size_t)(r+8)*N + c) = make_float2(acc[mi][ni][2], acc[mi][ni][3]);
        }
    }
}

// ---------------- RoPE + transposes ----------------------------------------
__global__ void rope_q_kernel(const float* __restrict__ cs, const float* __restrict__ sn){
    int idx = blockIdx.x*256 + threadIdx.x;     // MM*HH*64 pairs
    int i  = idx & 63;
    int h  = (idx >> 6) & (HH-1);
    int bs = idx >> 10;
    int s  = bs & (SS-1);
    int b  = bs >> 11;
    const float* src = g_Qp + ((size_t)bs*HH + h)*HD + 2*i;
    float xr = src[0], xi = src[1];
    float c = cs[s*64+i], si = sn[s*64+i];
    float* dst = g_Qt + (((size_t)(b*HH+h)*SS + s)*HD) + 2*i;
    dst[0] = xr*c - xi*si;
    dst[1] = xr*si + xi*c;
}
__global__ void rope_k_kernel(const float* __restrict__ cs, const float* __restrict__ sn){
    int idx = blockIdx.x*256 + threadIdx.x;     // MM*KVH*64 pairs
    int i  = idx & 63;
    int h  = (idx >> 6) & (KVH-1);
    int bs = idx >> 8;
    int s  = bs & (SS-1);
    int b  = bs >> 11;
    const float* src = g_Kp + ((size_t)bs*KVH + h)*HD + 2*i;
    float xr = src[0], xi = src[1];
    float c = cs[s*64+i], si = sn[s*64+i];
    float* dst = g_Kt + (((size_t)(b*KVH+h)*SS + s)*HD) + 2*i;
    dst[0] = xr*c - xi*si;
    dst[1] = xr*si + xi*c;
}
__global__ void vtrans_kernel(){
    int idx = blockIdx.x*256 + threadIdx.x;     // MM*KVD/4 float4s
    int d4 = idx & 31;
    int h  = (idx >> 5) & (KVH-1);
    int bs = idx >> 7;
    int s  = bs & (SS-1);
    int b  = bs >> 11;
    float4 v = *(const float4*)(g_Vp + (size_t)idx*4);
    *(float4*)(g_Vt + (((size_t)(b*KVH+h)*SS + s)*HD) + d4*4) = v;
}

// ---------------- flash attention (fp32 SIMT, causal) ----------------------
// grid: (32 q-tiles, B*H=32); block 256 thr = 16(tx=cols/d) x 16(ty=rows)
#define FLASH_SMEM ((64*132 + 64*128 + 64*128 + 64*68)*4)

__global__ void __launch_bounds__(256) flash_kernel(){
    extern __shared__ float smf[];
    float* Qs = smf;              // [64][132]  (pad: rows 4 apart hit diff banks)
    float* Ks = smf + 64*132;     // [64][128]  XOR-swizzled d-chunks
    float* Vs = Ks  + 64*128;     // [64][128]
    float* Ps = Vs  + 64*128;     // [64][68]

    const int qt = blockIdx.x;
    const int bh = blockIdx.y;
    const int b = bh >> 4, h = bh & 15;
    const int kvh = h >> 2;
    const int q0 = qt * 64;
    const int tid = threadIdx.x;
    const int tx = tid & 15, ty = tid >> 4;

    const float* Qg = g_Qt + (size_t)(b*HH + h)   * SS * HD;
    const float* Kg = g_Kt + (size_t)(b*KVH + kvh)* SS * HD;
    const float* Vg = g_Vt + (size_t)(b*KVH + kvh)* SS * HD;

    for (int i = tid; i < 64*32; i += 256) {
        int row = i >> 5, dc = i & 31;
        *(float4*)(Qs + row*132 + dc*4) =
            *(const float4*)(Qg + (size_t)(q0+row)*HD + dc*4);
    }

    float m_r[4], l_r[4], O[4][8];
    #pragma unroll
    for (int i=0;i<4;i++){
        m_r[i] = -INFINITY; l_r[i] = 0.f;
        #pragma unroll
        for (int j=0;j<8;j++) O[i][j]=0.f;
    }
    const float scale = 0.08838834764831845f;  // 1/sqrt(128)

    for (int kti = 0; kti <= qt; kti++) {
        int k0 = kti * 64;
        __syncthreads();                      // Ps/Ks/Vs consumers done
        for (int i = tid; i < 64*32; i += 256) {
            int row = i >> 5, dc = i & 31;
            int pc = dc ^ ((row >> 2) & 7);   // swizzle: conflict-free K reads
            *(float4*)(Ks + row*128 + pc*4) =
                *(const float4*)(Kg + (size_t)(k0+row)*HD + dc*4);
            *(float4*)(Vs + row*128 + dc*4) =
                *(const float4*)(Vg + (size_t)(k0+row)*HD + dc*4);
        }
        __syncthreads();

        float acc[4][4];
        #pragma unroll
        for (int i=0;i<4;i++)
            #pragma unroll
            for(int j=0;j<4;j++) acc[i][j]=0.f;

        #pragma unroll 4
        for (int dc = 0; dc < 32; dc++) {
            float4 qv[4], kv[4];
            #pragma unroll
            for (int i=0;i<4;i++)
                qv[i] = *(const float4*)(Qs + (ty*4+i)*132 + dc*4);
            int pc = (dc ^ (tx & 7)) * 4;
            #pragma unroll
            for (int j=0;j<4;j++)
                kv[j] = *(const float4*)(Ks + (tx*4+j)*128 + pc);
            #pragma unroll
            for (int i=0;i<4;i++)
                #pragma unroll
                for (int j=0;j<4;j++)
                    acc[i][j] += qv[i].x*kv[j].x + qv[i].y*kv[j].y
                               + qv[i].z*kv[j].z + qv[i].w*kv[j].w;
        }

        const bool diag = (kti == qt);
        #pragma unroll
        for (int i=0;i<4;i++){
            int qi = q0 + ty*4 + i;
            float mt = -INFINITY;
            #pragma unroll
            for (int j=0;j<4;j++){
                float s = acc[i][j]*scale;
                if (diag && (k0 + tx*4 + j > qi)) s = -INFINITY;
                acc[i][j] = s;
                mt = fmaxf(mt, s);
            }
            #pragma unroll
            for (int o=8;o>=1;o>>=1)
                mt = fmaxf(mt, __shfl_xor_sync(0xffffffffu, mt, o));
            float mn  = fmaxf(m_r[i], mt);
            float fac = __expf(m_r[i] - mn);
            float sum = 0.f;
            #pragma unroll
            for (int j=0;j<4;j++){
                float p = __expf(acc[i][j] - mn);
                acc[i][j] = p;
                sum += p;
            }
            #pragma unroll
            for (int o=8;o>=1;o>>=1)
                sum += __shfl_xor_sync(0xffffffffu, sum, o);
            l_r[i] = l_r[i]*fac + sum;
            m_r[i] = mn;
            #pragma unroll
            for (int j=0;j<8;j++) O[i][j] *= fac;
            #pragma unroll
            for (int j=0;j<4;j++)
                Ps[(ty*4+i)*68 + tx*4 + j] = acc[i][j];
        }
        __syncthreads();

        #pragma unroll 2
        for (int k=0;k<64;k++){
            float pk[4];
            #pragma unroll
            for (int i=0;i<4;i++) pk[i] = Ps[(ty*4+i)*68 + k];
            float4 v0 = *(const float4*)(Vs + k*128 + tx*8);
            float4 v1 = *(const float4*)(Vs + k*128 + tx*8 + 4);
            #pragma unroll
            for (int i=0;i<4;i++){
                O[i][0] += pk[i]*v0.x; O[i][1] += pk[i]*v0.y;
                O[i][2] += pk[i]*v0.z; O[i][3] += pk[i]*v0.w;
                O[i][4] += pk[i]*v1.x; O[i][5] += pk[i]*v1.y;
                O[i][6] += pk[i]*v1.z; O[i][7] += pk[i]*v1.w;
            }
        }
    }

    #pragma unroll
    for (int i=0;i<4;i++){
        float inv = 1.f / l_r[i];
        int q = q0 + ty*4 + i;
        float* dst = g_AttO + ((size_t)(b*SS) + q)*DD + h*HD + tx*8;
        *(float4*)dst     = make_float4(O[i][0]*inv, O[i][1]*inv, O[i][2]*inv, O[i][3]*inv);
        *(float4*)(dst+4) = make_float4(O[i][4]*inv, O[i][5]*inv, O[i][6]*inv, O[i][7]*inv);
    }
}

// ---------------- launch ----------------------------------------------------
extern "C" void kernel_launch(void* const* d_in, const int* in_sizes, int n_in,
                              void* d_out, int out_size){
    const float* x  = (const float*)d_in[0];
    const float* fc = (const float*)d_in[1];
    const float* fs = (const float*)d_in[2];
    const float* wq = (const float*)d_in[3];
    const float* wk = (const float*)d_in[4];
    const float* wv = (const float*)d_in[5];
    const float* wo = (const float*)d_in[6];
    float* out = (float*)d_out;

    float *pQp, *pKp, *pVp, *pAo;
    cudaGetSymbolAddress((void**)&pQp, g_Qp);
    cudaGetSymbolAddress((void**)&pKp, g_Kp);
    cudaGetSymbolAddress((void**)&pVp, g_Vp);
    cudaGetSymbolAddress((void**)&pAo, g_AttO);

    cudaFuncSetAttribute(flash_kernel,
        cudaFuncAttributeMaxDynamicSharedMemorySize, FLASH_SMEM);

    gemm_tf32<<<dim3(16,32),256>>>(x, wq, pQp, 2048, 2048);
    gemm_tf32<<<dim3( 4,32),256>>>(x, wk, pKp,  512, 2048);
    gemm_tf32<<<dim3( 4,32),256>>>(x, wv, pVp,  512, 2048);
    rope_q_kernel<<<(MM*HH*64)/256, 256>>>(fc, fs);
    rope_k_kernel<<<(MM*KVH*64)/256, 256>>>(fc, fs);
    vtrans_kernel<<<(MM*KVD/4)/256, 256>>>();
    flash_kernel<<<dim3(32,32),256,FLASH_SMEM>>>();
    gemm_tf32<<<dim3(16,32),256>>>(pAo, wo, out, 2048, 2048);
}

// round 7
// speedup vs baseline: 1.0420x; 1.0129x over previous
#include <cuda_runtime.h>
#include <math.h>
#include <stdint.h>

#define BB 2
#define SS 2048
#define DD 2048
#define HH 16
#define KVH 4
#define HD 128
#define MM (BB*SS)        // 4096 rows
#define KVD (KVH*HD)      // 512

// ---------------- scratch (device globals; no allocation allowed) ----------
__device__ float g_Qp[(size_t)MM*DD];    // x @ wq^T            [b,s,h,d]
__device__ float g_Kp[(size_t)MM*KVD];   // x @ wk^T            [b,s,kh,d]
__device__ float g_Vp[(size_t)MM*KVD];   // x @ wv^T            [b,s,kh,d]
__device__ float g_Qt[(size_t)MM*DD];    // roped, transposed   [b,h,s,d]
__device__ float g_Kt[(size_t)MM*KVD];   // roped, transposed   [b,kh,s,d]
__device__ float g_Vt[(size_t)MM*KVD];   // transposed          [b,kh,s,d]
__device__ float g_AttO[(size_t)MM*DD];  // attention out       [b,s,h*d]

// ---------------- tf32 helpers ---------------------------------------------
__device__ __forceinline__ uint32_t f2tf(float x){
    uint32_t u; asm("cvt.rna.tf32.f32 %0, %1;" : "=r"(u) : "f"(x)); return u;
}
__device__ __forceinline__ void mma8(float* c, const uint32_t* a, const uint32_t* b){
    asm volatile("mma.sync.aligned.m16n8k8.row.col.f32.tf32.tf32.f32 "
        "{%0,%1,%2,%3}, {%4,%5,%6,%7}, {%8,%9}, {%0,%1,%2,%3};"
        : "+f"(c[0]),"+f"(c[1]),"+f"(c[2]),"+f"(c[3])
        : "r"(a[0]),"r"(a[1]),"r"(a[2]),"r"(a[3]),"r"(b[0]),"r"(b[1]));
}

// ---------------- GEMM: C[M,N] = A[M,K] @ W[N,K]^T (tf32 accum fp32) -------
// block tile 128x128, K-step 32, 8 warps (2m x 4n), warp tile 64x32.
// Register-staged prefetch: next k-tile LDGs issue before the MMA block so
// gmem latency hides under tensor work.
__global__ void __launch_bounds__(256) gemm_tf32(const float* __restrict__ A,
                                                 const float* __restrict__ W,
                                                 float* __restrict__ C,
                                                 int N, int K)
{
    __shared__ uint32_t As[32][132];   // [k][m], +4 pad -> conflict-free frags
    __shared__ uint32_t Bs[32][132];   // [k][n]
    const int tid  = threadIdx.x;
    const int warp = tid >> 5, lane = tid & 31;
    const int g = lane >> 2, t = lane & 3;
    const int wm = warp & 1, wn = warp >> 1;
    const int m0 = blockIdx.y * 128, n0 = blockIdx.x * 128;

    int lrow[4], lkc[4];
    #pragma unroll
    for (int i=0;i<4;i++){ int idx = tid + i*256; lrow[i]=idx>>3; lkc[i]=(idx&7)<<2; }
    const float* Ab = A + (size_t)m0*K;
    const float* Wb = W + (size_t)n0*K;

    float acc[4][4][4];
    #pragma unroll
    for (int a=0;a<4;a++)
        #pragma unroll
        for (int b2=0;b2<4;b2++)
            #pragma unroll
            for (int c=0;c<4;c++) acc[a][b2][c]=0.f;

    float4 ra[4], rb[4];
    #pragma unroll
    for (int i=0;i<4;i++){
        ra[i] = *(const float4*)(Ab + (size_t)lrow[i]*K + lkc[i]);
        rb[i] = *(const float4*)(Wb + (size_t)lrow[i]*K + lkc[i]);
    }

    for (int kt = 0; kt < K; kt += 32) {
        #pragma unroll
        for (int i = 0; i < 4; i++) {
            As[lkc[i]+0][lrow[i]]=f2tf(ra[i].x); As[lkc[i]+1][lrow[i]]=f2tf(ra[i].y);
            As[lkc[i]+2][lrow[i]]=f2tf(ra[i].z); As[lkc[i]+3][lrow[i]]=f2tf(ra[i].w);
            Bs[lkc[i]+0][lrow[i]]=f2tf(rb[i].x); Bs[lkc[i]+1][lrow[i]]=f2tf(rb[i].y);
            Bs[lkc[i]+2][lrow[i]]=f2tf(rb[i].z); Bs[lkc[i]+3][lrow[i]]=f2tf(rb[i].w);
        }
        __syncthreads();
        if (kt + 32 < K) {
            #pragma unroll
            for (int i = 0; i < 4; i++) {
                ra[i] = *(const float4*)(Ab + (size_t)lrow[i]*K + kt + 32 + lkc[i]);
                rb[i] = *(const float4*)(Wb + (size_t)lrow[i]*K + kt + 32 + lkc[i]);
            }
        }
        #pragma unroll
        for (int kk = 0; kk < 32; kk += 8) {
            uint32_t af[4][4], bf[4][2];
            #pragma unroll
            for (int mi=0; mi<4; mi++){
                int r = wm*64 + mi*16 + g;
                af[mi][0] = As[kk+t  ][r];
                af[mi][1] = As[kk+t  ][r+8];
                af[mi][2] = As[kk+t+4][r];
                af[mi][3] = As[kk+t+4][r+8];
            }
            #pragma unroll
            for (int ni=0; ni<4; ni++){
                int c = wn*32 + ni*8 + g;
                bf[ni][0] = Bs[kk+t  ][c];
                bf[ni][1] = Bs[kk+t+4][c];
            }
            #pragma unroll
            for (int mi=0; mi<4; mi++)
                #pragma unroll
                for (int ni=0; ni<4; ni++)
                    mma8(acc[mi][ni], af[mi], bf[ni]);
        }
        __syncthreads();
    }
    #pragma unroll
    for (int mi=0; mi<4; mi++){
        int r = m0 + wm*64 + mi*16 + g;
        #pragma unroll
        for (int ni=0; ni<4; ni++){
            int c = n0 + wn*32 + ni*8 + 2*t;
            *(float2*)(C + (size_t)r*N + c)     = make_float2(acc[mi][ni][0], acc[mi][ni][1]);
            *(float2*)(C + (size_t)(r+8)*N + c) = make_float2(acc[mi][ni][2], acc[mi][ni][3]);
        }
    }
}

// ---------------- RoPE + transposes ----------------------------------------
__global__ void rope_q_kernel(const float* __restrict__ cs, const float* __restrict__ sn){
    int idx = blockIdx.x*256 + threadIdx.x;     // MM*HH*64 pairs
    int i  = idx & 63;
    int h  = (idx >> 6) & (HH-1);
    int bs = idx >> 10;
    int s  = bs & (SS-1);
    int b  = bs >> 11;
    const float* src = g_Qp + ((size_t)bs*HH + h)*HD + 2*i;
    float xr = src[0], xi = src[1];
    float c = cs[s*64+i], si = sn[s*64+i];
    float* dst = g_Qt + (((size_t)(b*HH+h)*SS + s)*HD) + 2*i;
    dst[0] = xr*c - xi*si;
    dst[1] = xr*si + xi*c;
}
__global__ void rope_k_kernel(const float* __restrict__ cs, const float* __restrict__ sn){
    int idx = blockIdx.x*256 + threadIdx.x;     // MM*KVH*64 pairs
    int i  = idx & 63;
    int h  = (idx >> 6) & (KVH-1);
    int bs = idx >> 8;
    int s  = bs & (SS-1);
    int b  = bs >> 11;
    const float* src = g_Kp + ((size_t)bs*KVH + h)*HD + 2*i;
    float xr = src[0], xi = src[1];
    float c = cs[s*64+i], si = sn[s*64+i];
    float* dst = g_Kt + (((size_t)(b*KVH+h)*SS + s)*HD) + 2*i;
    dst[0] = xr*c - xi*si;
    dst[1] = xr*si + xi*c;
}
__global__ void vtrans_kernel(){
    int idx = blockIdx.x*256 + threadIdx.x;     // MM*KVD/4 float4s
    int d4 = idx & 31;
    int h  = (idx >> 5) & (KVH-1);
    int bs = idx >> 7;
    int s  = bs & (SS-1);
    int b  = bs >> 11;
    float4 v = *(const float4*)(g_Vp + (size_t)idx*4);
    *(float4*)(g_Vt + (((size_t)(b*KVH+h)*SS + s)*HD) + d4*4) = v;
}

// ---------------- tensor-core flash attention (tf32 mma, causal) -----------
// grid: (32 q-tiles heaviest-first, B*H=32); 256 thr = 8 warps.
// Warp grid for S (64x64): wm=warp&3 (16 rows), wn=warp>>2 (32 cols).
// Warp grid for O (64x128): wm rows, wn picks 64-wide d half.
// smem word offsets:
#define FQ_OFF 0          // Qs [64][132] tf32 (pre-scaled by 1/sqrt(HD))
#define FK_OFF 8448       // Ks [64][132] tf32
#define FV_OFF 16896      // Vs [64][132] tf32
#define FP_OFF 25344      // Ps [64][68]  tf32 probs
#define FRM_OFF 29696     // RedM [2][64] float
#define FRS_OFF 29824     // RedS [2][64] float
#define FLASH_SMEM ((29952)*4)

__global__ void __launch_bounds__(256) flash_tc_kernel(){
    extern __shared__ uint32_t sm[];
    uint32_t* Qs = sm + FQ_OFF;
    uint32_t* Ks = sm + FK_OFF;
    uint32_t* Vs = sm + FV_OFF;
    uint32_t* Ps = sm + FP_OFF;
    float* RedM = (float*)(sm + FRM_OFF);
    float* RedS = (float*)(sm + FRS_OFF);

    const int qt = 31 - blockIdx.x;          // heaviest tiles first
    const int bh = blockIdx.y;
    const int b = bh >> 4, h = bh & 15;
    const int kvh = h >> 2;
    const int q0 = qt * 64;
    const int tid = threadIdx.x;
    const int warp = tid >> 5, lane = tid & 31;
    const int g = lane >> 2, t = lane & 3;
    const int wm = warp & 3, wn = warp >> 2;
    const int r0 = wm * 16;

    const float* Qg = g_Qt + (size_t)(b*HH + h)   * SS * HD;
    const float* Kg = g_Kt + (size_t)(b*KVH + kvh)* SS * HD;
    const float* Vg = g_Vt + (size_t)(b*KVH + kvh)* SS * HD;

    const float qscale = 0.08838834764831845f;  // 1/sqrt(128), folded into Q
    for (int i = tid; i < 64*32; i += 256) {
        int r = i >> 5, dc = (i & 31) * 4;
        float4 v = *(const float4*)(Qg + (size_t)(q0+r)*HD + dc);
        Qs[r*132+dc  ] = f2tf(v.x*qscale);
        Qs[r*132+dc+1] = f2tf(v.y*qscale);
        Qs[r*132+dc+2] = f2tf(v.z*qscale);
        Qs[r*132+dc+3] = f2tf(v.w*qscale);
    }

    float O[8][4];
    #pragma unroll
    for (int ni=0;ni<8;ni++)
        #pragma unroll
        for (int j=0;j<4;j++) O[ni][j]=0.f;
    float m_r[2] = {-INFINITY,-INFINITY};
    float l_r[2] = {0.f,0.f};

    for (int kti = 0; kti <= qt; kti++) {
        int k0 = kti * 64;
        __syncthreads();                          // prev PV/QK done with Ks/Vs
        for (int i = tid; i < 64*32; i += 256) {
            int r = i >> 5, dc = (i & 31) * 4;
            float4 kv = *(const float4*)(Kg + (size_t)(k0+r)*HD + dc);
            Ks[r*132+dc  ]=f2tf(kv.x); Ks[r*132+dc+1]=f2tf(kv.y);
            Ks[r*132+dc+2]=f2tf(kv.z); Ks[r*132+dc+3]=f2tf(kv.w);
            float4 vv = *(const float4*)(Vg + (size_t)(k0+r)*HD + dc);
            Vs[r*132+dc  ]=f2tf(vv.x); Vs[r*132+dc+1]=f2tf(vv.y);
            Vs[r*132+dc+2]=f2tf(vv.z); Vs[r*132+dc+3]=f2tf(vv.w);
        }
        __syncthreads();

        // ---- S = Q @ K^T on the tensor pipe -----------------------------
        float sc[4][4];
        #pragma unroll
        for (int ni=0;ni<4;ni++)
            #pragma unroll
            for (int j=0;j<4;j++) sc[ni][j]=0.f;
        #pragma unroll
        for (int ks = 0; ks < 16; ks++) {
            int kc = ks * 8;
            uint32_t a[4];
            a[0]=Qs[(r0+g  )*132 + kc+t  ];
            a[1]=Qs[(r0+g+8)*132 + kc+t  ];
            a[2]=Qs[(r0+g  )*132 + kc+t+4];
            a[3]=Qs[(r0+g+8)*132 + kc+t+4];
            #pragma unroll
            for (int ni=0;ni<4;ni++){
                int n = wn*32 + ni*8 + g;
                uint32_t bfr[2];
                bfr[0]=Ks[n*132 + kc+t  ];
                bfr[1]=Ks[n*132 + kc+t+4];
                mma8(sc[ni], a, bfr);
            }
        }

        if (kti == qt) {                          // causal mask on diagonal
            int rg0 = q0 + r0 + g, rg1 = rg0 + 8;
            #pragma unroll
            for (int ni=0;ni<4;ni++){
                int ck = k0 + wn*32 + ni*8 + 2*t;
                if (ck   > rg0) sc[ni][0] = -INFINITY;
                if (ck+1 > rg0) sc[ni][1] = -INFINITY;
                if (ck   > rg1) sc[ni][2] = -INFINITY;
                if (ck+1 > rg1) sc[ni][3] = -INFINITY;
            }
        }

        // ---- online softmax on fragments --------------------------------
        float mx0 = -INFINITY, mx1 = -INFINITY;
        #pragma unroll
        for (int ni=0;ni<4;ni++){
            mx0 = fmaxf(mx0, fmaxf(sc[ni][0], sc[ni][1]));
            mx1 = fmaxf(mx1, fmaxf(sc[ni][2], sc[ni][3]));
        }
        mx0 = fmaxf(mx0, __shfl_xor_sync(0xffffffffu, mx0, 1));
        mx0 = fmaxf(mx0, __shfl_xor_sync(0xffffffffu, mx0, 2));
        mx1 = fmaxf(mx1, __shfl_xor_sync(0xffffffffu, mx1, 1));
        mx1 = fmaxf(mx1, __shfl_xor_sync(0xffffffffu, mx1, 2));
        if (t == 0) {
            RedM[wn*64 + r0+g  ] = mx0;
            RedM[wn*64 + r0+g+8] = mx1;
        }
        __syncthreads();
        float mt0 = fmaxf(RedM[r0+g  ], RedM[64 + r0+g  ]);
        float mt1 = fmaxf(RedM[r0+g+8], RedM[64 + r0+g+8]);
        float mn0 = fmaxf(m_r[0], mt0), mn1 = fmaxf(m_r[1], mt1);
        float f0 = __expf(m_r[0] - mn0), f1 = __expf(m_r[1] - mn1);
        m_r[0] = mn0; m_r[1] = mn1;

        float s0 = 0.f, s1 = 0.f;
        #pragma unroll
        for (int ni=0;ni<4;ni++){
            float p0 = __expf(sc[ni][0] - mn0);
            float p1 = __expf(sc[ni][1] - mn0);
            float p2 = __expf(sc[ni][2] - mn1);
            float p3 = __expf(sc[ni][3] - mn1);
            s0 += p0 + p1; s1 += p2 + p3;
            int c = wn*32 + ni*8 + 2*t;
            Ps[(r0+g  )*68 + c  ] = f2tf(p0);
            Ps[(r0+g  )*68 + c+1] = f2tf(p1);
            Ps[(r0+g+8)*68 + c  ] = f2tf(p2);
            Ps[(r0+g+8)*68 + c+1] = f2tf(p3);
        }
        s0 += __shfl_xor_sync(0xffffffffu, s0, 1);
        s0 += __shfl_xor_sync(0xffffffffu, s0, 2);
        s1 += __shfl_xor_sync(0xffffffffu, s1, 1);
        s1 += __shfl_xor_sync(0xffffffffu, s1, 2);
        if (t == 0) {
            RedS[wn*64 + r0+g  ] = s0;
            RedS[wn*64 + r0+g+8] = s1;
        }
        #pragma unroll
        for (int ni=0;ni<8;ni++){
            O[ni][0] *= f0; O[ni][1] *= f0;
            O[ni][2] *= f1; O[ni][3] *= f1;
        }
        __syncthreads();                          // Ps + sums visible
        l_r[0] = l_r[0]*f0 + RedS[r0+g  ] + RedS[64 + r0+g  ];
        l_r[1] = l_r[1]*f1 + RedS[r0+g+8] + RedS[64 + r0+g+8];

        // ---- O += P @ V on the tensor pipe ------------------------------
        #pragma unroll
        for (int ks = 0; ks < 8; ks++) {
            int kc = ks * 8;
            uint32_t a[4];
            a[0]=Ps[(r0+g  )*68 + kc+t  ];
            a[1]=Ps[(r0+g+8)*68 + kc+t  ];
            a[2]=Ps[(r0+g  )*68 + kc+t+4];
            a[3]=Ps[(r0+g+8)*68 + kc+t+4];
            #pragma unroll
            for (int ni=0;ni<8;ni++){
                int d = wn*64 + ni*8 + g;
                uint32_t bfr[2];
                bfr[0]=Vs[(kc+t  )*132 + d];
                bfr[1]=Vs[(kc+t+4)*132 + d];
                mma8(O[ni], a, bfr);
            }
        }
    }

    float inv0 = 1.f / l_r[0], inv1 = 1.f / l_r[1];
    int rg0 = q0 + r0 + g, rg1 = rg0 + 8;
    #pragma unroll
    for (int ni=0;ni<8;ni++){
        int c = h*HD + wn*64 + ni*8 + 2*t;
        *(float2*)(g_AttO + ((size_t)(b*SS)+rg0)*DD + c) =
            make_float2(O[ni][0]*inv0, O[ni][1]*inv0);
        *(float2*)(g_AttO + ((size_t)(b*SS)+rg1)*DD + c) =
            make_float2(O[ni][2]*inv1, O[ni][3]*inv1);
    }
}

// ---------------- launch ----------------------------------------------------
extern "C" void kernel_launch(void* const* d_in, const int* in_sizes, int n_in,
                              void* d_out, int out_size){
    const float* x  = (const float*)d_in[0];
    const float* fc = (const float*)d_in[1];
    const float* fs = (const float*)d_in[2];
    const float* wq = (const float*)d_in[3];
    const float* wk = (const float*)d_in[4];
    const float* wv = (const float*)d_in[5];
    const float* wo = (const float*)d_in[6];
    float* out = (float*)d_out;

    float *pQp, *pKp, *pVp, *pAo;
    cudaGetSymbolAddress((void**)&pQp, g_Qp);
    cudaGetSymbolAddress((void**)&pKp, g_Kp);
    cudaGetSymbolAddress((void**)&pVp, g_Vp);
    cudaGetSymbolAddress((void**)&pAo, g_AttO);

    cudaFuncSetAttribute(flash_tc_kernel,
        cudaFuncAttributeMaxDynamicSharedMemorySize, FLASH_SMEM);

    gemm_tf32<<<dim3(16,32),256>>>(x, wq, pQp, 2048, 2048);
    gemm_tf32<<<dim3( 4,32),256>>>(x, wk, pKp,  512, 2048);
    gemm_tf32<<<dim3( 4,32),256>>>(x, wv, pVp,  512, 2048);
    rope_q_kernel<<<(MM*HH*64)/256, 256>>>(fc, fs);
    rope_k_kernel<<<(MM*KVH*64)/256, 256>>>(fc, fs);
    vtrans_kernel<<<(MM*KVD/4)/256, 256>>>();
    flash_tc_kernel<<<dim3(32,32),256,FLASH_SMEM>>>();
    gemm_tf32<<<dim3(16,32),256>>>(pAo, wo, out, 2048, 2048);
}

// round 9
// speedup vs baseline: 3.1601x; 3.0328x over previous
#include <cuda_runtime.h>
#include <cuda_fp16.h>
#include <math.h>
#include <stdint.h>

#define BB 2
#define SS 2048
#define DD 2048
#define HH 16
#define KVH 4
#define HD 128
#define MM (BB*SS)        // 4096 rows
#define KVD (KVH*HD)      // 512

// ---------------- scratch (device globals; no allocation allowed) ----------
__device__ float    g_Qp[(size_t)MM*DD];      // x @ wq^T          [b,s,h,d] f32
__device__ float    g_Kp[(size_t)MM*KVD];     // x @ wk^T          f32
__device__ float    g_Vp[(size_t)MM*KVD];     // x @ wv^T          f32
__device__ uint32_t g_QtW[(size_t)MM*DD/2];   // roped+scaled, half2 words [b,h,s,d]
__device__ uint32_t g_KtW[(size_t)MM*KVD/2];  // roped, half2 words [b,kh,s,d]
__device__ uint32_t g_VtW[(size_t)MM*KVD/2];  // half2 words        [b,kh,s,d]
__device__ float    g_AttO[(size_t)MM*DD];    // attention out      [b,s,h*d] f32

// ---------------- fp16 helpers ----------------------------------------------
__device__ __forceinline__ uint32_t f2h2(float x, float y){
    __half2 h = __floats2half2_rn(x, y);       // .x = low = first elem
    return *(uint32_t*)&h;
}
__device__ __forceinline__ void mma16(float* c, const uint32_t* a, const uint32_t* b){
    asm volatile("mma.sync.aligned.m16n8k16.row.col.f32.f16.f16.f32 "
        "{%0,%1,%2,%3}, {%4,%5,%6,%7}, {%8,%9}, {%0,%1,%2,%3};"
        : "+f"(c[0]),"+f"(c[1]),"+f"(c[2]),"+f"(c[3])
        : "r"(a[0]),"r"(a[1]),"r"(a[2]),"r"(a[3]),"r"(b[0]),"r"(b[1]));
}

// ---------------- GEMM: C[M,N] = A[M,K] @ W[N,K]^T (f16 mma, f32 accum) ----
// block tile 128x128, K-step 32 floats (16 half2 words), 8 warps (2m x 4n).
__global__ void __launch_bounds__(256) gemm_f16(const float* __restrict__ A,
                                                const float* __restrict__ W,
                                                float* __restrict__ C,
                                                int N, int K)
{
    __shared__ uint32_t As[16][132];   // [kword][m], half2 words, +4 pad
    __shared__ uint32_t Bs[16][132];   // [kword][n]
    const int tid  = threadIdx.x;
    const int warp = tid >> 5, lane = tid & 31;
    const int g = lane >> 2, t = lane & 3;
    const int wm = warp & 1, wn = warp >> 1;
    const int m0 = blockIdx.y * 128, n0 = blockIdx.x * 128;

    int lrow[4], lkc[4];
    #pragma unroll
    for (int i=0;i<4;i++){ int idx = tid + i*256; lrow[i]=idx>>3; lkc[i]=(idx&7)<<2; }
    const float* Ab = A + (size_t)m0*K;
    const float* Wb = W + (size_t)n0*K;

    float acc[4][4][4];
    #pragma unroll
    for (int a=0;a<4;a++)
        #pragma unroll
        for (int b2=0;b2<4;b2++)
            #pragma unroll
            for (int c=0;c<4;c++) acc[a][b2][c]=0.f;

    float4 ra[4], rb[4];
    #pragma unroll
    for (int i=0;i<4;i++){
        ra[i] = *(const float4*)(Ab + (size_t)lrow[i]*K + lkc[i]);
        rb[i] = *(const float4*)(Wb + (size_t)lrow[i]*K + lkc[i]);
    }

    for (int kt = 0; kt < K; kt += 32) {
        #pragma unroll
        for (int i = 0; i < 4; i++) {
            int w0 = lkc[i] >> 1;              // word index 0,2,...,14
            As[w0  ][lrow[i]] = f2h2(ra[i].x, ra[i].y);
            As[w0+1][lrow[i]] = f2h2(ra[i].z, ra[i].w);
            Bs[w0  ][lrow[i]] = f2h2(rb[i].x, rb[i].y);
            Bs[w0+1][lrow[i]] = f2h2(rb[i].z, rb[i].w);
        }
        __syncthreads();
        if (kt + 32 < K) {
            #pragma unroll
            for (int i = 0; i < 4; i++) {
                ra[i] = *(const float4*)(Ab + (size_t)lrow[i]*K + kt + 32 + lkc[i]);
                rb[i] = *(const float4*)(Wb + (size_t)lrow[i]*K + kt + 32 + lkc[i]);
            }
        }
        #pragma unroll
        for (int kk = 0; kk < 16; kk += 8) {   // two k16 groups per tile
            uint32_t af[4][4], bf[4][2];
            #pragma unroll
            for (int mi=0; mi<4; mi++){
                int r = wm*64 + mi*16 + g;
                af[mi][0] = As[kk+t  ][r];
                af[mi][1] = As[kk+t  ][r+8];
                af[mi][2] = As[kk+t+4][r];
                af[mi][3] = As[kk+t+4][r+8];
            }
            #pragma unroll
            for (int ni=0; ni<4; ni++){
                int c = wn*32 + ni*8 + g;
                bf[ni][0] = Bs[kk+t  ][c];
                bf[ni][1] = Bs[kk+t+4][c];
            }
            #pragma unroll
            for (int mi=0; mi<4; mi++)
                #pragma unroll
                for (int ni=0; ni<4; ni++)
                    mma16(acc[mi][ni], af[mi], bf[ni]);
        }
        __syncthreads();
    }
    #pragma unroll
    for (int mi=0; mi<4; mi++){
        int r = m0 + wm*64 + mi*16 + g;
        #pragma unroll
        for (int ni=0; ni<4; ni++){
            int c = n0 + wn*32 + ni*8 + 2*t;
            *(float2*)(C + (size_t)r*N + c)     = make_float2(acc[mi][ni][0], acc[mi][ni][1]);
            *(float2*)(C + (size_t)(r+8)*N + c) = make_float2(acc[mi][ni][2], acc[mi][ni][3]);
        }
    }
}

// ---------------- RoPE + transposes (write half2 words) ---------------------
__global__ void rope_q_kernel(const float* __restrict__ cs, const float* __restrict__ sn){
    int idx = blockIdx.x*256 + threadIdx.x;     // MM*HH*64 pairs
    int i  = idx & 63;
    int h  = (idx >> 6) & (HH-1);
    int bs = idx >> 10;
    int s  = bs & (SS-1);
    int b  = bs >> 11;
    const float* src = g_Qp + ((size_t)bs*HH + h)*HD + 2*i;
    float xr = src[0], xi = src[1];
    float c = cs[s*64+i], si = sn[s*64+i];
    const float qscale = 0.08838834764831845f;  // 1/sqrt(128) folded here
    g_QtW[((size_t)(b*HH+h)*SS + s)*64 + i] =
        f2h2((xr*c - xi*si)*qscale, (xr*si + xi*c)*qscale);
}
// fused rope_k (blocks 0..4095) + v transpose (blocks 4096..6143)
__global__ void prep_kv_kernel(const float* __restrict__ cs, const float* __restrict__ sn){
    int bx = blockIdx.x;
    if (bx < 4096) {
        int idx = bx*256 + threadIdx.x;         // MM*KVH*64 pairs
        int i  = idx & 63;
        int h  = (idx >> 6) & (KVH-1);
        int bs = idx >> 8;
        int s  = bs & (SS-1);
        int b  = bs >> 11;
        const float* src = g_Kp + ((size_t)bs*KVH + h)*HD + 2*i;
        float xr = src[0], xi = src[1];
        float c = cs[s*64+i], si = sn[s*64+i];
        g_KtW[((size_t)(b*KVH+h)*SS + s)*64 + i] =
            f2h2(xr*c - xi*si, xr*si + xi*c);
    } else {
        int idx = (bx-4096)*256 + threadIdx.x;  // MM*KVD/4 float4s
        int d4 = idx & 31;
        int h  = (idx >> 5) & (KVH-1);
        int bs = idx >> 7;
        int s  = bs & (SS-1);
        int b  = bs >> 11;
        float4 v = *(const float4*)(g_Vp + (size_t)idx*4);
        uint32_t* dst = g_VtW + (((size_t)(b*KVH+h)*SS + s)*64) + d4*2;
        dst[0] = f2h2(v.x, v.y);
        dst[1] = f2h2(v.z, v.w);
    }
}

// ---------------- tensor-core flash attention (f16 mma, causal) -------------
// grid: (32 q-tiles heaviest-first, B*H=32); 256 thr = 8 warps.
// S warps: wm=warp&3 (16 rows), wn=warp>>2 (32 cols). O: wn picks 64-wide d half.
// smem u32-word offsets (all 16B aligned):
#define FQ_OFF 0          // Qs [64][68] half2 words (Q pre-scaled)
#define FK_OFF 4352       // Ks [64][68]
#define FV_OFF 8704       // Vs [64][68]  row-major [k][d] (ldmatrix.trans source)
#define FP_OFF 13056      // Ps [64][36]  half2 prob words
#define FRM_OFF 15360     // RedM [2][64] float
#define FRS_OFF 15488     // RedS [2][64] float
#define FLASH_SMEM (15616*4)

__global__ void __launch_bounds__(256) flash_f16_kernel(){
    extern __shared__ uint32_t sm[];
    uint32_t* Qs = sm + FQ_OFF;
    uint32_t* Ks = sm + FK_OFF;
    uint32_t* Vs = sm + FV_OFF;
    uint32_t* Ps = sm + FP_OFF;
    float* RedM = (float*)(sm + FRM_OFF);
    float* RedS = (float*)(sm + FRS_OFF);
    const uint32_t vbase = (uint32_t)__cvta_generic_to_shared(Vs);

    const int qt = 31 - blockIdx.x;          // heaviest tiles first
    const int bh = blockIdx.y;
    const int b = bh >> 4, h = bh & 15;
    const int kvh = h >> 2;
    const int q0 = qt * 64;
    const int tid = threadIdx.x;
    const int warp = tid >> 5, lane = tid & 31;
    const int g = lane >> 2, t = lane & 3;
    const int wm = warp & 3, wn = warp >> 2;
    const int r0 = wm * 16;

    const uint32_t* Qg = g_QtW + (size_t)(b*HH + h)   * SS * 64;
    const uint32_t* Kg = g_KtW + (size_t)(b*KVH + kvh)* SS * 64;
    const uint32_t* Vg = g_VtW + (size_t)(b*KVH + kvh)* SS * 64;

    for (int i = tid; i < 64*16; i += 256) {       // Q: 64 rows x 16 uint4
        int r = i >> 4, w4 = (i & 15) * 4;
        *(uint4*)(Qs + r*68 + w4) = *(const uint4*)(Qg + (size_t)(q0+r)*64 + w4);
    }

    float O[8][4];
    #pragma unroll
    for (int ni=0;ni<8;ni++)
        #pragma unroll
        for (int j=0;j<4;j++) O[ni][j]=0.f;
    float m_r[2] = {-INFINITY,-INFINITY};
    float l_r[2] = {0.f,0.f};

    for (int kti = 0; kti <= qt; kti++) {
        int k0 = kti * 64;
        __syncthreads();                          // prev consumers done with Ks/Vs
        for (int i = tid; i < 64*16; i += 256) {
            int r = i >> 4, w4 = (i & 15) * 4;
            *(uint4*)(Ks + r*68 + w4) = *(const uint4*)(Kg + (size_t)(k0+r)*64 + w4);
            *(uint4*)(Vs + r*68 + w4) = *(const uint4*)(Vg + (size_t)(k0+r)*64 + w4);
        }
        __syncthreads();

        // ---- S = Q @ K^T (f16 mma, k = HD = 8 groups of 16) --------------
        float sc[4][4];
        #pragma unroll
        for (int ni=0;ni<4;ni++)
            #pragma unroll
            for (int j=0;j<4;j++) sc[ni][j]=0.f;
        #pragma unroll
        for (int ks = 0; ks < 8; ks++) {
            int base = ks * 8;                     // word offset of k16 group
            uint32_t a[4];
            a[0]=Qs[(r0+g  )*68 + base+t  ];
            a[1]=Qs[(r0+g+8)*68 + base+t  ];
            a[2]=Qs[(r0+g  )*68 + base+t+4];
            a[3]=Qs[(r0+g+8)*68 + base+t+4];
            #pragma unroll
            for (int ni=0;ni<4;ni++){
                int n = wn*32 + ni*8 + g;
                uint32_t bfr[2];
                bfr[0]=Ks[n*68 + base+t  ];
                bfr[1]=Ks[n*68 + base+t+4];
                mma16(sc[ni], a, bfr);
            }
        }

        if (kti == qt) {                          // causal mask on diagonal
            int rg0 = q0 + r0 + g, rg1 = rg0 + 8;
            #pragma unroll
            for (int ni=0;ni<4;ni++){
                int ck = k0 + wn*32 + ni*8 + 2*t;
                if (ck   > rg0) sc[ni][0] = -INFINITY;
                if (ck+1 > rg0) sc[ni][1] = -INFINITY;
                if (ck   > rg1) sc[ni][2] = -INFINITY;
                if (ck+1 > rg1) sc[ni][3] = -INFINITY;
            }
        }

        // ---- online softmax on fragments --------------------------------
        float mx0 = -INFINITY, mx1 = -INFINITY;
        #pragma unroll
        for (int ni=0;ni<4;ni++){
            mx0 = fmaxf(mx0, fmaxf(sc[ni][0], sc[ni][1]));
            mx1 = fmaxf(mx1, fmaxf(sc[ni][2], sc[ni][3]));
        }
        mx0 = fmaxf(mx0, __shfl_xor_sync(0xffffffffu, mx0, 1));
        mx0 = fmaxf(mx0, __shfl_xor_sync(0xffffffffu, mx0, 2));
        mx1 = fmaxf(mx1, __shfl_xor_sync(0xffffffffu, mx1, 1));
        mx1 = fmaxf(mx1, __shfl_xor_sync(0xffffffffu, mx1, 2));
        if (t == 0) {
            RedM[wn*64 + r0+g  ] = mx0;
            RedM[wn*64 + r0+g+8] = mx1;
        }
        __syncthreads();
        float mt0 = fmaxf(RedM[r0+g  ], RedM[64 + r0+g  ]);
        float mt1 = fmaxf(RedM[r0+g+8], RedM[64 + r0+g+8]);
        float mn0 = fmaxf(m_r[0], mt0), mn1 = fmaxf(m_r[1], mt1);
        float f0 = __expf(m_r[0] - mn0), f1 = __expf(m_r[1] - mn1);
        m_r[0] = mn0; m_r[1] = mn1;

        float s0 = 0.f, s1 = 0.f;
        #pragma unroll
        for (int ni=0;ni<4;ni++){
            float p0 = __expf(sc[ni][0] - mn0);
            float p1 = __expf(sc[ni][1] - mn0);
            float p2 = __expf(sc[ni][2] - mn1);
            float p3 = __expf(sc[ni][3] - mn1);
            s0 += p0 + p1; s1 += p2 + p3;
            int w = wn*16 + ni*4 + t;             // word = col/2
            Ps[(r0+g  )*36 + w] = f2h2(p0, p1);
            Ps[(r0+g+8)*36 + w] = f2h2(p2, p3);
        }
        s0 += __shfl_xor_sync(0xffffffffu, s0, 1);
        s0 += __shfl_xor_sync(0xffffffffu, s0, 2);
        s1 += __shfl_xor_sync(0xffffffffu, s1, 1);
        s1 += __shfl_xor_sync(0xffffffffu, s1, 2);
        if (t == 0) {
            RedS[wn*64 + r0+g  ] = s0;
            RedS[wn*64 + r0+g+8] = s1;
        }
        #pragma unroll
        for (int ni=0;ni<8;ni++){
            O[ni][0] *= f0; O[ni][1] *= f0;
            O[ni][2] *= f1; O[ni][3] *= f1;
        }
        __syncthreads();                          // Ps + sums visible
        l_r[0] = l_r[0]*f0 + RedS[r0+g  ] + RedS[64 + r0+g  ];
        l_r[1] = l_r[1]*f1 + RedS[r0+g+8] + RedS[64 + r0+g+8];

        // ---- O += P @ V (f16 mma; V B-frags via ldmatrix.trans) ----------
        #pragma unroll
        for (int ks = 0; ks < 4; ks++) {          // 64 kseq = 4 groups of 16
            int base = ks * 8;
            uint32_t a[4];
            a[0]=Ps[(r0+g  )*36 + base+t  ];
            a[1]=Ps[(r0+g+8)*36 + base+t  ];
            a[2]=Ps[(r0+g  )*36 + base+t+4];
            a[3]=Ps[(r0+g+8)*36 + base+t+4];
            #pragma unroll
            for (int p = 0; p < 4; p++) {         // d16 pair -> ni 2p, 2p+1
                uint32_t b0,b1,b2,b3;
                uint32_t addr = vbase
                    + (uint32_t)((ks*16 + (lane & 15)) * 272        // row k: 68 words
                    + (wn*64 + p*16 + ((lane >> 4) << 3)) * 2);     // col d in halves
                asm volatile(
                    "ldmatrix.sync.aligned.m8n8.x4.trans.shared.b16 {%0,%1,%2,%3}, [%4];"
                    : "=r"(b0),"=r"(b1),"=r"(b2),"=r"(b3) : "r"(addr));
                uint32_t bb0[2]={b0,b1}, bb1[2]={b2,b3};
                mma16(O[2*p],   a, bb0);
                mma16(O[2*p+1], a, bb1);
            }
        }
    }

    float inv0 = 1.f / l_r[0], inv1 = 1.f / l_r[1];
    int rg0 = q0 + r0 + g, rg1 = rg0 + 8;
    #pragma unroll
    for (int ni=0;ni<8;ni++){
        int c = h*HD + wn*64 + ni*8 + 2*t;
        *(float2*)(g_AttO + ((size_t)(b*SS)+rg0)*DD + c) =
            make_float2(O[ni][0]*inv0, O[ni][1]*inv0);
        *(float2*)(g_AttO + ((size_t)(b*SS)+rg1)*DD + c) =
            make_float2(O[ni][2]*inv1, O[ni][3]*inv1);
    }
}

// ---------------- launch ----------------------------------------------------
extern "C" void kernel_launch(void* const* d_in, const int* in_sizes, int n_in,
                              void* d_out, int out_size){
    const float* x  = (const float*)d_in[0];
    const float* fc = (const float*)d_in[1];
    const float* fs = (const float*)d_in[2];
    const float* wq = (const float*)d_in[3];
    const float* wk = (const float*)d_in[4];
    const float* wv = (const float*)d_in[5];
    const float* wo = (const float*)d_in[6];
    float* out = (float*)d_out;

    float *pQp, *pKp, *pVp, *pAo;
    cudaGetSymbolAddress((void**)&pQp, g_Qp);
    cudaGetSymbolAddress((void**)&pKp, g_Kp);
    cudaGetSymbolAddress((void**)&pVp, g_Vp);
    cudaGetSymbolAddress((void**)&pAo, g_AttO);

    cudaFuncSetAttribute(flash_f16_kernel,
        cudaFuncAttributeMaxDynamicSharedMemorySize, FLASH_SMEM);

    // launch order keeps flash at index 5 for the -s 5 -c 1 ncu capture
    gemm_f16<<<dim3(16,32),256>>>(x, wq, pQp, 2048, 2048);          // 0
    gemm_f16<<<dim3( 4,32),256>>>(x, wk, pKp,  512, 2048);          // 1
    gemm_f16<<<dim3( 4,32),256>>>(x, wv, pVp,  512, 2048);          // 2
    rope_q_kernel<<<(MM*HH*64)/256, 256>>>(fc, fs);                 // 3
    prep_kv_kernel<<<6144, 256>>>(fc, fs);                          // 4
    flash_f16_kernel<<<dim3(32,32),256,FLASH_SMEM>>>();             // 5
    gemm_f16<<<dim3(16,32),256>>>(pAo, wo, out, 2048, 2048);        // 6
}

// round 10
// speedup vs baseline: 4.8635x; 1.5390x over previous
#include <cuda_runtime.h>
#include <cuda_fp16.h>
#include <math.h>
#include <stdint.h>

#define BB 2
#define SS 2048
#define DD 2048
#define HH 16
#define KVH 4
#define HD 128
#define MM (BB*SS)        // 4096 rows
#define KVD (KVH*HD)      // 512

// ---------------- scratch (device globals; no allocation allowed) ----------
__device__ uint32_t g_xh [(size_t)MM*DD/2];    // x as half2 words
__device__ uint32_t g_wqh[(size_t)DD*DD/2];
__device__ uint32_t g_wkh[(size_t)KVD*DD/2];
__device__ uint32_t g_wvh[(size_t)KVD*DD/2];
__device__ uint32_t g_woh[(size_t)DD*DD/2];
__device__ uint32_t g_QtW[(size_t)MM*DD/2];    // roped+scaled Q  [b,h,s,d] half2
__device__ uint32_t g_KtW[(size_t)MM*KVD/2];   // roped K         [b,kh,s,d]
__device__ uint32_t g_VtW[(size_t)MM*KVD/2];   // V               [b,kh,s,d]
__device__ uint32_t g_AttOh[(size_t)MM*DD/2];  // attention out   [b,s,h*d] half2

// ---------------- helpers ----------------------------------------------------
__device__ __forceinline__ uint32_t f2h2(float x, float y){
    __half2 h = __floats2half2_rn(x, y);       // .x = low = first elem
    return *(uint32_t*)&h;
}
__device__ __forceinline__ void mma16(float* c, const uint32_t* a, const uint32_t* b){
    asm volatile("mma.sync.aligned.m16n8k16.row.col.f32.f16.f16.f32 "
        "{%0,%1,%2,%3}, {%4,%5,%6,%7}, {%8,%9}, {%0,%1,%2,%3};"
        : "+f"(c[0]),"+f"(c[1]),"+f"(c[2]),"+f"(c[3])
        : "r"(a[0]),"r"(a[1]),"r"(a[2]),"r"(a[3]),"r"(b[0]),"r"(b[1]));
}
__device__ __forceinline__ void ldmx4(uint32_t* r, uint32_t addr){
    asm volatile("ldmatrix.sync.aligned.m8n8.x4.shared.b16 {%0,%1,%2,%3}, [%4];"
        : "=r"(r[0]),"=r"(r[1]),"=r"(r[2]),"=r"(r[3]) : "r"(addr));
}
#define CP_ASYNC16(dst, src) \
    asm volatile("cp.async.cg.shared.global [%0], [%1], 16;" :: "r"(dst), "l"(src))
#define CP_COMMIT() asm volatile("cp.async.commit_group;")
#define CP_WAIT1()  asm volatile("cp.async.wait_group 1;" ::: "memory")
#define CP_WAIT0()  asm volatile("cp.async.wait_group 0;" ::: "memory")

// ---------------- fp32 -> fp16 conversion prep -------------------------------
// float4-granular: x(2097152) wq(1048576) wk(262144) wv(262144) wo(1048576)
__global__ void cvt_kernel(const float* __restrict__ x,  const float* __restrict__ wq,
                           const float* __restrict__ wk, const float* __restrict__ wv,
                           const float* __restrict__ wo){
    size_t i = (size_t)blockIdx.x*256 + threadIdx.x;   // float4 index
    const float* src; uint32_t* dst;
    if      (i < 2097152u)            { src = x;  dst = g_xh;                 }
    else if (i < 3145728u)            { src = wq; dst = g_wqh; i -= 2097152u; }
    else if (i < 3407872u)            { src = wk; dst = g_wkh; i -= 3145728u; }
    else if (i < 3670016u)            { src = wv; dst = g_wvh; i -= 3407872u; }
    else                              { src = wo; dst = g_woh; i -= 3670016u; }
    float4 v = ((const float4*)src)[i];
    dst[2*i]   = f2h2(v.x, v.y);
    dst[2*i+1] = f2h2(v.z, v.w);
}

// ---------------- half GEMM: C[M,N] = A[M,K] @ W[N,K]^T ---------------------
// A,W fp16 (as half2 words). Block tile 128x128, k-step 64 halves, cp.async
// double buffer, ldmatrix fragments, 8 warps (2m x 4n), warp tile 64x32.
// MODE: 0=Q (rope+scale->g_QtW), 1=K (rope->g_KtW), 2=V (->g_VtW), 3=f32 C.
#define GH_ROWB 144u                 // 64 halves + 8 pad = 144 bytes/row
#define GH_TILE (128u*GH_ROWB)       // 18432 B per operand tile
#define GH_BUF  (2u*GH_TILE)         // A+B per buffer
#define GH_SMEM (2*GH_BUF)           // 73728 B

template<int MODE>
__global__ void __launch_bounds__(256,2) gemm_h(const uint32_t* __restrict__ A,
                                                const uint32_t* __restrict__ W,
                                                float* __restrict__ C,
                                                const float* __restrict__ cs,
                                                const float* __restrict__ sn,
                                                int N, int K)
{
    extern __shared__ char smem[];
    const uint32_t sb = (uint32_t)__cvta_generic_to_shared(smem);
    const int tid  = threadIdx.x;
    const int warp = tid >> 5, lane = tid & 31;
    const int g = lane >> 2, t = lane & 3;
    const int wm = warp & 1, wn = warp >> 1;
    const int m0 = blockIdx.y * 128, n0 = blockIdx.x * 128;
    const int KW = K >> 1;                         // half2 words per row

    const uint32_t* Ag = A + (size_t)m0 * KW;
    const uint32_t* Wg = W + (size_t)n0 * KW;

    float acc[4][4][4];
    #pragma unroll
    for (int a=0;a<4;a++)
        #pragma unroll
        for (int b2=0;b2<4;b2++)
            #pragma unroll
            for (int c=0;c<4;c++) acc[a][b2][c]=0.f;

    // per-thread cp.async map: 4 (row,chunk) pairs per operand
    int crow[4], cch[4];
    #pragma unroll
    for (int j=0;j<4;j++){ int idx = tid + j*256; crow[j]=idx>>3; cch[j]=idx&7; }

    auto load_tile = [&](int buf, int ktw){
        uint32_t sA = sb + buf*GH_BUF;
        uint32_t sB = sA + GH_TILE;
        #pragma unroll
        for (int j=0;j<4;j++){
            uint32_t off = crow[j]*GH_ROWB + cch[j]*16;
            const uint32_t* ga = Ag + (size_t)crow[j]*KW + ktw + cch[j]*4;
            const uint32_t* gb = Wg + (size_t)crow[j]*KW + ktw + cch[j]*4;
            CP_ASYNC16(sA + off, ga);
            CP_ASYNC16(sB + off, gb);
        }
    };

    const int NT = KW / 32;                        // k64-half tiles
    load_tile(0, 0); CP_COMMIT();

    const int selA = lane >> 3, lr = lane & 7;
    for (int s2 = 0; s2 < NT; s2++){
        const int buf = s2 & 1;
        if (s2 + 1 < NT){ load_tile(buf^1, (s2+1)*32); CP_COMMIT(); CP_WAIT1(); }
        else            { CP_WAIT0(); }
        __syncthreads();

        uint32_t sA = sb + buf*GH_BUF + (wm*64)*GH_ROWB;
        uint32_t sB = sb + buf*GH_BUF + GH_TILE + (wn*32)*GH_ROWB;
        #pragma unroll
        for (int kg = 0; kg < 4; kg++){
            uint32_t af[4][4], bf[4][2];
            #pragma unroll
            for (int mi=0; mi<4; mi++){
                uint32_t addr = sA + (mi*16 + (selA&1)*8 + lr)*GH_ROWB
                                   + (kg*16 + (selA>>1)*8)*2;
                ldmx4(af[mi], addr);
            }
            #pragma unroll
            for (int np=0; np<2; np++){
                uint32_t r[4];
                uint32_t addr = sB + (np*16 + (selA>>1)*8 + lr)*GH_ROWB
                                   + (kg*16 + (selA&1)*8)*2;
                ldmx4(r, addr);
                bf[np*2  ][0]=r[0]; bf[np*2  ][1]=r[1];
                bf[np*2+1][0]=r[2]; bf[np*2+1][1]=r[3];
            }
            #pragma unroll
            for (int mi=0; mi<4; mi++)
                #pragma unroll
                for (int ni=0; ni<4; ni++)
                    mma16(acc[mi][ni], af[mi], bf[ni]);
        }
        __syncthreads();
    }

    // ---------------- fused epilogues ---------------------------------------
    const float qs = 0.08838834764831845f;         // 1/sqrt(128)
    #pragma unroll
    for (int mi=0; mi<4; mi++){
        int r  = m0 + wm*64 + mi*16 + g;
        int r2 = r + 8;
        if (MODE == 3){
            #pragma unroll
            for (int ni=0; ni<4; ni++){
                int c = n0 + wn*32 + ni*8 + 2*t;
                *(float2*)(C + (size_t)r *N + c) = make_float2(acc[mi][ni][0], acc[mi][ni][1]);
                *(float2*)(C + (size_t)r2*N + c) = make_float2(acc[mi][ni][2], acc[mi][ni][3]);
            }
        } else {
            int b0 = r >> 11,  s0 = r  & (SS-1);
            int b1 = r2 >> 11, s1 = r2 & (SS-1);
            #pragma unroll
            for (int ni=0; ni<4; ni++){
                int c = n0 + wn*32 + ni*8 + 2*t;
                int h = c >> 7;
                int i = (c & 127) >> 1;
                float a0=acc[mi][ni][0], a1=acc[mi][ni][1];
                float a2=acc[mi][ni][2], a3=acc[mi][ni][3];
                if (MODE == 0){
                    float cv0=cs[s0*64+i], sv0=sn[s0*64+i];
                    float cv1=cs[s1*64+i], sv1=sn[s1*64+i];
                    g_QtW[((size_t)(b0*HH+h)*SS + s0)*64 + i] =
                        f2h2((a0*cv0 - a1*sv0)*qs, (a0*sv0 + a1*cv0)*qs);
                    g_QtW[((size_t)(b1*HH+h)*SS + s1)*64 + i] =
                        f2h2((a2*cv1 - a3*sv1)*qs, (a2*sv1 + a3*cv1)*qs);
                } else if (MODE == 1){
                    float cv0=cs[s0*64+i], sv0=sn[s0*64+i];
                    float cv1=cs[s1*64+i], sv1=sn[s1*64+i];
                    g_KtW[((size_t)(b0*KVH+h)*SS + s0)*64 + i] =
                        f2h2(a0*cv0 - a1*sv0, a0*sv0 + a1*cv0);
                    g_KtW[((size_t)(b1*KVH+h)*SS + s1)*64 + i] =
                        f2h2(a2*cv1 - a3*sv1, a2*sv1 + a3*cv1);
                } else {  // MODE == 2 (V): plain transpose to half2
                    g_VtW[((size_t)(b0*KVH+h)*SS + s0)*64 + i] = f2h2(a0, a1);
                    g_VtW[((size_t)(b1*KVH+h)*SS + s1)*64 + i] = f2h2(a2, a3);
                }
            }
        }
    }
}

// ---------------- tensor-core flash attention (f16 mma, causal) -------------
// grid: (32 q-tiles heaviest-first, B*H=32); 256 thr = 8 warps.
#define FQ_OFF 0          // Qs [64][68] half2 words (Q pre-scaled)
#define FK_OFF 4352       // Ks [64][68]
#define FV_OFF 8704       // Vs [64][68]  row-major [k][d] (ldmatrix.trans source)
#define FP_OFF 13056      // Ps [64][36]  half2 prob words
#define FRM_OFF 15360     // RedM [2][64] float
#define FRS_OFF 15488     // RedS [2][64] float
#define FLASH_SMEM (15616*4)

__global__ void __launch_bounds__(256) flash_f16_kernel(){
    extern __shared__ uint32_t sm[];
    uint32_t* Qs = sm + FQ_OFF;
    uint32_t* Ks = sm + FK_OFF;
    uint32_t* Vs = sm + FV_OFF;
    uint32_t* Ps = sm + FP_OFF;
    float* RedM = (float*)(sm + FRM_OFF);
    float* RedS = (float*)(sm + FRS_OFF);
    const uint32_t vbase = (uint32_t)__cvta_generic_to_shared(Vs);

    const int qt = 31 - blockIdx.x;          // heaviest tiles first
    const int bh = blockIdx.y;
    const int b = bh >> 4, h = bh & 15;
    const int kvh = h >> 2;
    const int q0 = qt * 64;
    const int tid = threadIdx.x;
    const int warp = tid >> 5, lane = tid & 31;
    const int g = lane >> 2, t = lane & 3;
    const int wm = warp & 3, wn = warp >> 2;
    const int r0 = wm * 16;

    const uint32_t* Qg = g_QtW + (size_t)(b*HH + h)   * SS * 64;
    const uint32_t* Kg = g_KtW + (size_t)(b*KVH + kvh)* SS * 64;
    const uint32_t* Vg = g_VtW + (size_t)(b*KVH + kvh)* SS * 64;

    for (int i = tid; i < 64*16; i += 256) {       // Q: 64 rows x 16 uint4
        int r = i >> 4, w4 = (i & 15) * 4;
        *(uint4*)(Qs + r*68 + w4) = *(const uint4*)(Qg + (size_t)(q0+r)*64 + w4);
    }

    float O[8][4];
    #pragma unroll
    for (int ni=0;ni<8;ni++)
        #pragma unroll
        for (int j=0;j<4;j++) O[ni][j]=0.f;
    float m_r[2] = {-INFINITY,-INFINITY};
    float l_r[2] = {0.f,0.f};

    for (int kti = 0; kti <= qt; kti++) {
        int k0 = kti * 64;
        __syncthreads();                          // prev consumers done with Ks/Vs
        for (int i = tid; i < 64*16; i += 256) {
            int r = i >> 4, w4 = (i & 15) * 4;
            *(uint4*)(Ks + r*68 + w4) = *(const uint4*)(Kg + (size_t)(k0+r)*64 + w4);
            *(uint4*)(Vs + r*68 + w4) = *(const uint4*)(Vg + (size_t)(k0+r)*64 + w4);
        }
        __syncthreads();

        // ---- S = Q @ K^T (f16 mma, k = HD = 8 groups of 16) --------------
        float sc[4][4];
        #pragma unroll
        for (int ni=0;ni<4;ni++)
            #pragma unroll
            for (int j=0;j<4;j++) sc[ni][j]=0.f;
        #pragma unroll
        for (int ks = 0; ks < 8; ks++) {
            int base = ks * 8;                     // word offset of k16 group
            uint32_t a[4];
            a[0]=Qs[(r0+g  )*68 + base+t  ];
            a[1]=Qs[(r0+g+8)*68 + base+t  ];
            a[2]=Qs[(r0+g  )*68 + base+t+4];
            a[3]=Qs[(r0+g+8)*68 + base+t+4];
            #pragma unroll
            for (int ni=0;ni<4;ni++){
                int n = wn*32 + ni*8 + g;
                uint32_t bfr[2];
                bfr[0]=Ks[n*68 + base+t  ];
                bfr[1]=Ks[n*68 + base+t+4];
                mma16(sc[ni], a, bfr);
            }
        }

        if (kti == qt) {                          // causal mask on diagonal
            int rg0 = q0 + r0 + g, rg1 = rg0 + 8;
            #pragma unroll
            for (int ni=0;ni<4;ni++){
                int ck = k0 + wn*32 + ni*8 + 2*t;
                if (ck   > rg0) sc[ni][0] = -INFINITY;
                if (ck+1 > rg0) sc[ni][1] = -INFINITY;
                if (ck   > rg1) sc[ni][2] = -INFINITY;
                if (ck+1 > rg1) sc[ni][3] = -INFINITY;
            }
        }

        // ---- online softmax on fragments --------------------------------
        float mx0 = -INFINITY, mx1 = -INFINITY;
        #pragma unroll
        for (int ni=0;ni<4;ni++){
            mx0 = fmaxf(mx0, fmaxf(sc[ni][0], sc[ni][1]));
            mx1 = fmaxf(mx1, fmaxf(sc[ni][2], sc[ni][3]));
        }
        mx0 = fmaxf(mx0, __shfl_xor_sync(0xffffffffu, mx0, 1));
        mx0 = fmaxf(mx0, __shfl_xor_sync(0xffffffffu, mx0, 2));
        mx1 = fmaxf(mx1, __shfl_xor_sync(0xffffffffu, mx1, 1));
        mx1 = fmaxf(mx1, __shfl_xor_sync(0xffffffffu, mx1, 2));
        if (t == 0) {
            RedM[wn*64 + r0+g  ] = mx0;
            RedM[wn*64 + r0+g+8] = mx1;
        }
        __syncthreads();
        float mt0 = fmaxf(RedM[r0+g  ], RedM[64 + r0+g  ]);
        float mt1 = fmaxf(RedM[r0+g+8], RedM[64 + r0+g+8]);
        float mn0 = fmaxf(m_r[0], mt0), mn1 = fmaxf(m_r[1], mt1);
        float f0 = __expf(m_r[0] - mn0), f1 = __expf(m_r[1] - mn1);
        m_r[0] = mn0; m_r[1] = mn1;

        float s0 = 0.f, s1 = 0.f;
        #pragma unroll
        for (int ni=0;ni<4;ni++){
            float p0 = __expf(sc[ni][0] - mn0);
            float p1 = __expf(sc[ni][1] - mn0);
            float p2 = __expf(sc[ni][2] - mn1);
            float p3 = __expf(sc[ni][3] - mn1);
            s0 += p0 + p1; s1 += p2 + p3;
            int w = wn*16 + ni*4 + t;             // word = col/2
            Ps[(r0+g  )*36 + w] = f2h2(p0, p1);
            Ps[(r0+g+8)*36 + w] = f2h2(p2, p3);
        }
        s0 += __shfl_xor_sync(0xffffffffu, s0, 1);
        s0 += __shfl_xor_sync(0xffffffffu, s0, 2);
        s1 += __shfl_xor_sync(0xffffffffu, s1, 1);
        s1 += __shfl_xor_sync(0xffffffffu, s1, 2);
        if (t == 0) {
            RedS[wn*64 + r0+g  ] = s0;
            RedS[wn*64 + r0+g+8] = s1;
        }
        #pragma unroll
        for (int ni=0;ni<8;ni++){
            O[ni][0] *= f0; O[ni][1] *= f0;
            O[ni][2] *= f1; O[ni][3] *= f1;
        }
        __syncthreads();                          // Ps + sums visible
        l_r[0] = l_r[0]*f0 + RedS[r0+g  ] + RedS[64 + r0+g  ];
        l_r[1] = l_r[1]*f1 + RedS[r0+g+8] + RedS[64 + r0+g+8];

        // ---- O += P @ V (f16 mma; V B-frags via ldmatrix.trans) ----------
        #pragma unroll
        for (int ks = 0; ks < 4; ks++) {          // 64 kseq = 4 groups of 16
            int base = ks * 8;
            uint32_t a[4];
            a[0]=Ps[(r0+g  )*36 + base+t  ];
            a[1]=Ps[(r0+g+8)*36 + base+t  ];
            a[2]=Ps[(r0+g  )*36 + base+t+4];
            a[3]=Ps[(r0+g+8)*36 + base+t+4];
            #pragma unroll
            for (int p = 0; p < 4; p++) {         // d16 pair -> ni 2p, 2p+1
                uint32_t b0,b1,b2,b3;
                uint32_t addr = vbase
                    + (uint32_t)((ks*16 + (lane & 15)) * 272        // row k: 68 words
                    + (wn*64 + p*16 + ((lane >> 4) << 3)) * 2);     // col d in halves
                asm volatile(
                    "ldmatrix.sync.aligned.m8n8.x4.trans.shared.b16 {%0,%1,%2,%3}, [%4];"
                    : "=r"(b0),"=r"(b1),"=r"(b2),"=r"(b3) : "r"(addr));
                uint32_t bb0[2]={b0,b1}, bb1[2]={b2,b3};
                mma16(O[2*p],   a, bb0);
                mma16(O[2*p+1], a, bb1);
            }
        }
    }

    float inv0 = 1.f / l_r[0], inv1 = 1.f / l_r[1];
    int rg0 = q0 + r0 + g, rg1 = rg0 + 8;
    #pragma unroll
    for (int ni=0;ni<8;ni++){
        int c = h*HD + wn*64 + ni*8 + 2*t;        // even
        int cw = c >> 1;
        g_AttOh[((size_t)(b*SS)+rg0)*(DD/2) + cw] = f2h2(O[ni][0]*inv0, O[ni][1]*inv0);
        g_AttOh[((size_t)(b*SS)+rg1)*(DD/2) + cw] = f2h2(O[ni][2]*inv1, O[ni][3]*inv1);
    }
}

// ---------------- launch ----------------------------------------------------
extern "C" void kernel_launch(void* const* d_in, const int* in_sizes, int n_in,
                              void* d_out, int out_size){
    const float* x  = (const float*)d_in[0];
    const float* fc = (const float*)d_in[1];
    const float* fs = (const float*)d_in[2];
    const float* wq = (const float*)d_in[3];
    const float* wk = (const float*)d_in[4];
    const float* wv = (const float*)d_in[5];
    const float* wo = (const float*)d_in[6];
    float* out = (float*)d_out;

    uint32_t *pxh, *pwqh, *pwkh, *pwvh, *pwoh, *pAoh;
    cudaGetSymbolAddress((void**)&pxh,  g_xh);
    cudaGetSymbolAddress((void**)&pwqh, g_wqh);
    cudaGetSymbolAddress((void**)&pwkh, g_wkh);
    cudaGetSymbolAddress((void**)&pwvh, g_wvh);
    cudaGetSymbolAddress((void**)&pwoh, g_woh);
    cudaGetSymbolAddress((void**)&pAoh, g_AttOh);

    cudaFuncSetAttribute(gemm_h<0>, cudaFuncAttributeMaxDynamicSharedMemorySize, GH_SMEM);
    cudaFuncSetAttribute(gemm_h<1>, cudaFuncAttributeMaxDynamicSharedMemorySize, GH_SMEM);
    cudaFuncSetAttribute(gemm_h<2>, cudaFuncAttributeMaxDynamicSharedMemorySize, GH_SMEM);
    cudaFuncSetAttribute(gemm_h<3>, cudaFuncAttributeMaxDynamicSharedMemorySize, GH_SMEM);
    cudaFuncSetAttribute(flash_f16_kernel,
        cudaFuncAttributeMaxDynamicSharedMemorySize, FLASH_SMEM);

    cvt_kernel<<<18432, 256>>>(x, wq, wk, wv, wo);                         // 0
    gemm_h<0><<<dim3(16,32),256,GH_SMEM>>>(pxh, pwqh, nullptr, fc, fs, 2048, 2048); // 1
    gemm_h<1><<<dim3( 4,32),256,GH_SMEM>>>(pxh, pwkh, nullptr, fc, fs,  512, 2048); // 2
    gemm_h<2><<<dim3( 4,32),256,GH_SMEM>>>(pxh, pwvh, nullptr, fc, fs,  512, 2048); // 3
    flash_f16_kernel<<<dim3(32,32),256,FLASH_SMEM>>>();                    // 4
    gemm_h<3><<<dim3(16,32),256,GH_SMEM>>>(pAoh, pwoh, out, nullptr, nullptr, 2048, 2048); // 5
}

// round 11
// speedup vs baseline: 5.0320x; 1.0346x over previous
#include <cuda_runtime.h>
#include <cuda_fp16.h>
#include <math.h>
#include <stdint.h>

#define BB 2
#define SS 2048
#define DD 2048
#define HH 16
#define KVH 4
#define HD 128
#define MM (BB*SS)        // 4096 rows
#define KVD (KVH*HD)      // 512
#define NQKV (DD + 2*KVD) // 3072 stacked rows

// ---------------- scratch (device globals; no allocation allowed) ----------
__device__ uint32_t g_xh   [(size_t)MM*DD/2];     // x as half2 words
__device__ uint32_t g_wqkvh[(size_t)NQKV*DD/2];   // wq|wk|wv stacked, half2
__device__ uint32_t g_woh  [(size_t)DD*DD/2];
__device__ uint32_t g_QtW[(size_t)MM*DD/2];       // roped+scaled Q [b,h,s,d] half2
__device__ uint32_t g_KtW[(size_t)MM*KVD/2];      // roped K        [b,kh,s,d]
__device__ uint32_t g_VtW[(size_t)MM*KVD/2];      // V              [b,kh,s,d]
__device__ uint32_t g_AttOh[(size_t)MM*DD/2];     // attention out  [b,s,h*d] half2

// ---------------- helpers ----------------------------------------------------
__device__ __forceinline__ uint32_t f2h2(float x, float y){
    __half2 h = __floats2half2_rn(x, y);       // .x = low = first elem
    return *(uint32_t*)&h;
}
__device__ __forceinline__ void mma16(float* c, const uint32_t* a, const uint32_t* b){
    asm volatile("mma.sync.aligned.m16n8k16.row.col.f32.f16.f16.f32 "
        "{%0,%1,%2,%3}, {%4,%5,%6,%7}, {%8,%9}, {%0,%1,%2,%3};"
        : "+f"(c[0]),"+f"(c[1]),"+f"(c[2]),"+f"(c[3])
        : "r"(a[0]),"r"(a[1]),"r"(a[2]),"r"(a[3]),"r"(b[0]),"r"(b[1]));
}
__device__ __forceinline__ void ldmx4(uint32_t* r, uint32_t addr){
    asm volatile("ldmatrix.sync.aligned.m8n8.x4.shared.b16 {%0,%1,%2,%3}, [%4];"
        : "=r"(r[0]),"=r"(r[1]),"=r"(r[2]),"=r"(r[3]) : "r"(addr));
}
#define CP_ASYNC16(dst, src) \
    asm volatile("cp.async.cg.shared.global [%0], [%1], 16;" :: "r"(dst), "l"(src))
#define CP_COMMIT() asm volatile("cp.async.commit_group;")
#define CP_WAIT1()  asm volatile("cp.async.wait_group 1;" ::: "memory")
#define CP_WAIT0()  asm volatile("cp.async.wait_group 0;" ::: "memory")

// ---------------- fp32 -> fp16 conversion prep -------------------------------
// float4-granular. wq/wk/wv stack into g_wqkvh (rows 0-2047 | 2048-2559 | 2560-3071)
__global__ void cvt_kernel(const float* __restrict__ x,  const float* __restrict__ wq,
                           const float* __restrict__ wk, const float* __restrict__ wv,
                           const float* __restrict__ wo){
    size_t i = (size_t)blockIdx.x*256 + threadIdx.x;   // float4 index
    const float* src; uint32_t* dst;
    if      (i < 2097152u){ src = x;  dst = g_xh;                              }
    else if (i < 3145728u){ src = wq; dst = g_wqkvh;            i -= 2097152u; }
    else if (i < 3407872u){ src = wk; dst = g_wqkvh + 2097152u; i -= 3145728u; }
    else if (i < 3670016u){ src = wv; dst = g_wqkvh + 2621440u; i -= 3407872u; }
    else                  { src = wo; dst = g_woh;              i -= 3670016u; }
    float4 v = ((const float4*)src)[i];
    dst[2*i]   = f2h2(v.x, v.y);
    dst[2*i+1] = f2h2(v.z, v.w);
}

// ---------------- half GEMM: C[M,N] = A[M,K] @ W[N,K]^T ---------------------
// Block tile 128x128, k-step 64 halves, cp.async double buffer, ldmatrix
// fragments, 8 warps (2m x 4n), warp tile 64x32.
// MODE 0: fused QKV epilogue (dispatch by blockIdx.x: Q rope+scale / K rope / V)
// MODE 1: plain f32 C output (O-projection).
#define GH_ROWB 144u                 // 64 halves + 8 pad = 144 bytes/row
#define GH_TILE (128u*GH_ROWB)       // 18432 B per operand tile
#define GH_BUF  (2u*GH_TILE)         // A+B per buffer
#define GH_SMEM (2*GH_BUF)           // 73728 B

template<int MODE>
__global__ void __launch_bounds__(256,2) gemm_h(const uint32_t* __restrict__ A,
                                                const uint32_t* __restrict__ W,
                                                float* __restrict__ C,
                                                const float* __restrict__ cs,
                                                const float* __restrict__ sn,
                                                int N, int K)
{
    extern __shared__ char smem[];
    const uint32_t sb = (uint32_t)__cvta_generic_to_shared(smem);
    const int tid  = threadIdx.x;
    const int warp = tid >> 5, lane = tid & 31;
    const int g = lane >> 2, t = lane & 3;
    const int wm = warp & 1, wn = warp >> 1;
    const int m0 = blockIdx.y * 128, n0 = blockIdx.x * 128;
    const int KW = K >> 1;                         // half2 words per row

    const uint32_t* Ag = A + (size_t)m0 * KW;
    const uint32_t* Wg = W + (size_t)n0 * KW;

    float acc[4][4][4];
    #pragma unroll
    for (int a=0;a<4;a++)
        #pragma unroll
        for (int b2=0;b2<4;b2++)
            #pragma unroll
            for (int c=0;c<4;c++) acc[a][b2][c]=0.f;

    // per-thread cp.async map: 4 (row,chunk) pairs per operand
    int crow[4], cch[4];
    #pragma unroll
    for (int j=0;j<4;j++){ int idx = tid + j*256; crow[j]=idx>>3; cch[j]=idx&7; }

    auto load_tile = [&](int buf, int ktw){
        uint32_t sA = sb + buf*GH_BUF;
        uint32_t sB = sA + GH_TILE;
        #pragma unroll
        for (int j=0;j<4;j++){
            uint32_t off = crow[j]*GH_ROWB + cch[j]*16;
            const uint32_t* ga = Ag + (size_t)crow[j]*KW + ktw + cch[j]*4;
            const uint32_t* gb = Wg + (size_t)crow[j]*KW + ktw + cch[j]*4;
            CP_ASYNC16(sA + off, ga);
            CP_ASYNC16(sB + off, gb);
        }
    };

    const int NT = KW / 32;                        // k64-half tiles
    load_tile(0, 0); CP_COMMIT();

    const int selA = lane >> 3, lr = lane & 7;
    for (int s2 = 0; s2 < NT; s2++){
        const int buf = s2 & 1;
        if (s2 + 1 < NT){ load_tile(buf^1, (s2+1)*32); CP_COMMIT(); CP_WAIT1(); }
        else            { CP_WAIT0(); }
        __syncthreads();

        uint32_t sA = sb + buf*GH_BUF + (wm*64)*GH_ROWB;
        uint32_t sB = sb + buf*GH_BUF + GH_TILE + (wn*32)*GH_ROWB;
        #pragma unroll
        for (int kg = 0; kg < 4; kg++){
            uint32_t af[4][4], bf[4][2];
            #pragma unroll
            for (int mi=0; mi<4; mi++){
                uint32_t addr = sA + (mi*16 + (selA&1)*8 + lr)*GH_ROWB
                                   + (kg*16 + (selA>>1)*8)*2;
                ldmx4(af[mi], addr);
            }
            #pragma unroll
            for (int np=0; np<2; np++){
                uint32_t r[4];
                uint32_t addr = sB + (np*16 + (selA>>1)*8 + lr)*GH_ROWB
                                   + (kg*16 + (selA&1)*8)*2;
                ldmx4(r, addr);
                bf[np*2  ][0]=r[0]; bf[np*2  ][1]=r[1];
                bf[np*2+1][0]=r[2]; bf[np*2+1][1]=r[3];
            }
            #pragma unroll
            for (int mi=0; mi<4; mi++)
                #pragma unroll
                for (int ni=0; ni<4; ni++)
                    mma16(acc[mi][ni], af[mi], bf[ni]);
        }
        __syncthreads();
    }

    // ---------------- fused epilogues ---------------------------------------
    const float qs = 0.08838834764831845f;         // 1/sqrt(128)
    const int region = (MODE == 0) ? ((blockIdx.x < 16) ? 0 : (blockIdx.x < 20) ? 1 : 2) : 3;
    #pragma unroll
    for (int mi=0; mi<4; mi++){
        int r  = m0 + wm*64 + mi*16 + g;
        int r2 = r + 8;
        if (MODE == 1){
            #pragma unroll
            for (int ni=0; ni<4; ni++){
                int c = n0 + wn*32 + ni*8 + 2*t;
                *(float2*)(C + (size_t)r *N + c) = make_float2(acc[mi][ni][0], acc[mi][ni][1]);
                *(float2*)(C + (size_t)r2*N + c) = make_float2(acc[mi][ni][2], acc[mi][ni][3]);
            }
        } else {
            int b0 = r >> 11,  s0 = r  & (SS-1);
            int b1 = r2 >> 11, s1 = r2 & (SS-1);
            #pragma unroll
            for (int ni=0; ni<4; ni++){
                int c = n0 + wn*32 + ni*8 + 2*t;
                float a0=acc[mi][ni][0], a1=acc[mi][ni][1];
                float a2=acc[mi][ni][2], a3=acc[mi][ni][3];
                if (region == 0){                  // Q: rope + scale
                    int h = c >> 7, i = (c & 127) >> 1;
                    float cv0=cs[s0*64+i], sv0=sn[s0*64+i];
                    float cv1=cs[s1*64+i], sv1=sn[s1*64+i];
                    g_QtW[((size_t)(b0*HH+h)*SS + s0)*64 + i] =
                        f2h2((a0*cv0 - a1*sv0)*qs, (a0*sv0 + a1*cv0)*qs);
                    g_QtW[((size_t)(b1*HH+h)*SS + s1)*64 + i] =
                        f2h2((a2*cv1 - a3*sv1)*qs, (a2*sv1 + a3*cv1)*qs);
                } else if (region == 1){           // K: rope
                    int ck = c - 2048;
                    int h = ck >> 7, i = (ck & 127) >> 1;
                    float cv0=cs[s0*64+i], sv0=sn[s0*64+i];
                    float cv1=cs[s1*64+i], sv1=sn[s1*64+i];
                    g_KtW[((size_t)(b0*KVH+h)*SS + s0)*64 + i] =
                        f2h2(a0*cv0 - a1*sv0, a0*sv0 + a1*cv0);
                    g_KtW[((size_t)(b1*KVH+h)*SS + s1)*64 + i] =
                        f2h2(a2*cv1 - a3*sv1, a2*sv1 + a3*cv1);
                } else {                           // V: transpose only
                    int cv = c - 2560;
                    int h = cv >> 7, i = (cv & 127) >> 1;
                    g_VtW[((size_t)(b0*KVH+h)*SS + s0)*64 + i] = f2h2(a0, a1);
                    g_VtW[((size_t)(b1*KVH+h)*SS + s1)*64 + i] = f2h2(a2, a3);
                }
            }
        }
    }
}

// ---------------- tensor-core flash attention (f16 mma, causal) -------------
// grid: (32 q-tiles heaviest-first, B*H=32); 256 thr = 8 warps.
#define FQ_OFF 0          // Qs [64][68] half2 words (Q pre-scaled)
#define FK_OFF 4352       // Ks [64][68]
#define FV_OFF 8704       // Vs [64][68]  row-major [k][d] (ldmatrix.trans source)
#define FP_OFF 13056      // Ps [64][36]  half2 prob words
#define FRM_OFF 15360     // RedM [2][64] float
#define FRS_OFF 15488     // RedS [2][64] float
#define FLASH_SMEM (15616*4)

__global__ void __launch_bounds__(256) flash_f16_kernel(){
    extern __shared__ uint32_t sm[];
    uint32_t* Qs = sm + FQ_OFF;
    uint32_t* Ks = sm + FK_OFF;
    uint32_t* Vs = sm + FV_OFF;
    uint32_t* Ps = sm + FP_OFF;
    float* RedM = (float*)(sm + FRM_OFF);
    float* RedS = (float*)(sm + FRS_OFF);
    const uint32_t vbase = (uint32_t)__cvta_generic_to_shared(Vs);

    const int qt = 31 - blockIdx.x;          // heaviest tiles first
    const int bh = blockIdx.y;
    const int b = bh >> 4, h = bh & 15;
    const int kvh = h >> 2;
    const int q0 = qt * 64;
    const int tid = threadIdx.x;
    const int warp = tid >> 5, lane = tid & 31;
    const int g = lane >> 2, t = lane & 3;
    const int wm = warp & 3, wn = warp >> 2;
    const int r0 = wm * 16;

    const uint32_t* Qg = g_QtW + (size_t)(b*HH + h)   * SS * 64;
    const uint32_t* Kg = g_KtW + (size_t)(b*KVH + kvh)* SS * 64;
    const uint32_t* Vg = g_VtW + (size_t)(b*KVH + kvh)* SS * 64;

    for (int i = tid; i < 64*16; i += 256) {       // Q: 64 rows x 16 uint4
        int r = i >> 4, w4 = (i & 15) * 4;
        *(uint4*)(Qs + r*68 + w4) = *(const uint4*)(Qg + (size_t)(q0+r)*64 + w4);
    }

    float O[8][4];
    #pragma unroll
    for (int ni=0;ni<8;ni++)
        #pragma unroll
        for (int j=0;j<4;j++) O[ni][j]=0.f;
    float m_r[2] = {-INFINITY,-INFINITY};
    float l_r[2] = {0.f,0.f};

    for (int kti = 0; kti <= qt; kti++) {
        int k0 = kti * 64;
        __syncthreads();                          // prev consumers done with Ks/Vs
        for (int i = tid; i < 64*16; i += 256) {
            int r = i >> 4, w4 = (i & 15) * 4;
            *(uint4*)(Ks + r*68 + w4) = *(const uint4*)(Kg + (size_t)(k0+r)*64 + w4);
            *(uint4*)(Vs + r*68 + w4) = *(const uint4*)(Vg + (size_t)(k0+r)*64 + w4);
        }
        __syncthreads();

        // ---- S = Q @ K^T (f16 mma, k = HD = 8 groups of 16) --------------
        float sc[4][4];
        #pragma unroll
        for (int ni=0;ni<4;ni++)
            #pragma unroll
            for (int j=0;j<4;j++) sc[ni][j]=0.f;
        #pragma unroll
        for (int ks = 0; ks < 8; ks++) {
            int base = ks * 8;                     // word offset of k16 group
            uint32_t a[4];
            a[0]=Qs[(r0+g  )*68 + base+t  ];
            a[1]=Qs[(r0+g+8)*68 + base+t  ];
            a[2]=Qs[(r0+g  )*68 + base+t+4];
            a[3]=Qs[(r0+g+8)*68 + base+t+4];
            #pragma unroll
            for (int ni=0;ni<4;ni++){
                int n = wn*32 + ni*8 + g;
                uint32_t bfr[2];
                bfr[0]=Ks[n*68 + base+t  ];
                bfr[1]=Ks[n*68 + base+t+4];
                mma16(sc[ni], a, bfr);
            }
        }

        if (kti == qt) {                          // causal mask on diagonal
            int rg0 = q0 + r0 + g, rg1 = rg0 + 8;
            #pragma unroll
            for (int ni=0;ni<4;ni++){
                int ck = k0 + wn*32 + ni*8 + 2*t;
                if (ck   > rg0) sc[ni][0] = -INFINITY;
                if (ck+1 > rg0) sc[ni][1] = -INFINITY;
                if (ck   > rg1) sc[ni][2] = -INFINITY;
                if (ck+1 > rg1) sc[ni][3] = -INFINITY;
            }
        }

        // ---- online softmax on fragments --------------------------------
        float mx0 = -INFINITY, mx1 = -INFINITY;
        #pragma unroll
        for (int ni=0;ni<4;ni++){
            mx0 = fmaxf(mx0, fmaxf(sc[ni][0], sc[ni][1]));
            mx1 = fmaxf(mx1, fmaxf(sc[ni][2], sc[ni][3]));
        }
        mx0 = fmaxf(mx0, __shfl_xor_sync(0xffffffffu, mx0, 1));
        mx0 = fmaxf(mx0, __shfl_xor_sync(0xffffffffu, mx0, 2));
        mx1 = fmaxf(mx1, __shfl_xor_sync(0xffffffffu, mx1, 1));
        mx1 = fmaxf(mx1, __shfl_xor_sync(0xffffffffu, mx1, 2));
        if (t == 0) {
            RedM[wn*64 + r0+g  ] = mx0;
            RedM[wn*64 + r0+g+8] = mx1;
        }
        __syncthreads();
        float mt0 = fmaxf(RedM[r0+g  ], RedM[64 + r0+g  ]);
        float mt1 = fmaxf(RedM[r0+g+8], RedM[64 + r0+g+8]);
        float mn0 = fmaxf(m_r[0], mt0), mn1 = fmaxf(m_r[1], mt1);
        float f0 = __expf(m_r[0] - mn0), f1 = __expf(m_r[1] - mn1);
        m_r[0] = mn0; m_r[1] = mn1;

        float s0 = 0.f, s1 = 0.f;
        #pragma unroll
        for (int ni=0;ni<4;ni++){
            float p0 = __expf(sc[ni][0] - mn0);
            float p1 = __expf(sc[ni][1] - mn0);
            float p2 = __expf(sc[ni][2] - mn1);
            float p3 = __expf(sc[ni][3] - mn1);
            s0 += p0 + p1; s1 += p2 + p3;
            int w = wn*16 + ni*4 + t;             // word = col/2
            Ps[(r0+g  )*36 + w] = f2h2(p0, p1);
            Ps[(r0+g+8)*36 + w] = f2h2(p2, p3);
        }
        s0 += __shfl_xor_sync(0xffffffffu, s0, 1);
        s0 += __shfl_xor_sync(0xffffffffu, s0, 2);
        s1 += __shfl_xor_sync(0xffffffffu, s1, 1);
        s1 += __shfl_xor_sync(0xffffffffu, s1, 2);
        if (t == 0) {
            RedS[wn*64 + r0+g  ] = s0;
            RedS[wn*64 + r0+g+8] = s1;
        }
        #pragma unroll
        for (int ni=0;ni<8;ni++){
            O[ni][0] *= f0; O[ni][1] *= f0;
            O[ni][2] *= f1; O[ni][3] *= f1;
        }
        __syncthreads();                          // Ps + sums visible
        l_r[0] = l_r[0]*f0 + RedS[r0+g  ] + RedS[64 + r0+g  ];
        l_r[1] = l_r[1]*f1 + RedS[r0+g+8] + RedS[64 + r0+g+8];

        // ---- O += P @ V (f16 mma; V B-frags via ldmatrix.trans) ----------
        #pragma unroll
        for (int ks = 0; ks < 4; ks++) {          // 64 kseq = 4 groups of 16
            int base = ks * 8;
            uint32_t a[4];
            a[0]=Ps[(r0+g  )*36 + base+t  ];
            a[1]=Ps[(r0+g+8)*36 + base+t  ];
            a[2]=Ps[(r0+g  )*36 + base+t+4];
            a[3]=Ps[(r0+g+8)*36 + base+t+4];
            #pragma unroll
            for (int p = 0; p < 4; p++) {         // d16 pair -> ni 2p, 2p+1
                uint32_t b0,b1,b2,b3;
                uint32_t addr = vbase
                    + (uint32_t)((ks*16 + (lane & 15)) * 272        // row k: 68 words
                    + (wn*64 + p*16 + ((lane >> 4) << 3)) * 2);     // col d in halves
                asm volatile(
                    "ldmatrix.sync.aligned.m8n8.x4.trans.shared.b16 {%0,%1,%2,%3}, [%4];"
                    : "=r"(b0),"=r"(b1),"=r"(b2),"=r"(b3) : "r"(addr));
                uint32_t bb0[2]={b0,b1}, bb1[2]={b2,b3};
                mma16(O[2*p],   a, bb0);
                mma16(O[2*p+1], a, bb1);
            }
        }
    }

    float inv0 = 1.f / l_r[0], inv1 = 1.f / l_r[1];
    int rg0 = q0 + r0 + g, rg1 = rg0 + 8;
    #pragma unroll
    for (int ni=0;ni<8;ni++){
        int c = h*HD + wn*64 + ni*8 + 2*t;        // even
        int cw = c >> 1;
        g_AttOh[((size_t)(b*SS)+rg0)*(DD/2) + cw] = f2h2(O[ni][0]*inv0, O[ni][1]*inv0);
        g_AttOh[((size_t)(b*SS)+rg1)*(DD/2) + cw] = f2h2(O[ni][2]*inv1, O[ni][3]*inv1);
    }
}

// ---------------- launch ----------------------------------------------------
extern "C" void kernel_launch(void* const* d_in, const int* in_sizes, int n_in,
                              void* d_out, int out_size){
    const float* x  = (const float*)d_in[0];
    const float* fc = (const float*)d_in[1];
    const float* fs = (const float*)d_in[2];
    const float* wq = (const float*)d_in[3];
    const float* wk = (const float*)d_in[4];
    const float* wv = (const float*)d_in[5];
    const float* wo = (const float*)d_in[6];
    float* out = (float*)d_out;

    uint32_t *pxh, *pwqkvh, *pwoh, *pAoh;
    cudaGetSymbolAddress((void**)&pxh,    g_xh);
    cudaGetSymbolAddress((void**)&pwqkvh, g_wqkvh);
    cudaGetSymbolAddress((void**)&pwoh,   g_woh);
    cudaGetSymbolAddress((void**)&pAoh,   g_AttOh);

    cudaFuncSetAttribute(gemm_h<0>, cudaFuncAttributeMaxDynamicSharedMemorySize, GH_SMEM);
    cudaFuncSetAttribute(gemm_h<1>, cudaFuncAttributeMaxDynamicSharedMemorySize, GH_SMEM);
    cudaFuncSetAttribute(flash_f16_kernel,
        cudaFuncAttributeMaxDynamicSharedMemorySize, FLASH_SMEM);

    cvt_kernel<<<18432, 256>>>(x, wq, wk, wv, wo);                              // 0
    gemm_h<0><<<dim3(24,32),256,GH_SMEM>>>(pxh, pwqkvh, nullptr, fc, fs, NQKV, 2048); // 1
    flash_f16_kernel<<<dim3(32,32),256,FLASH_SMEM>>>();                         // 2
    gemm_h<1><<<dim3(16,32),256,GH_SMEM>>>(pAoh, pwoh, out, nullptr, nullptr, 2048, 2048); // 3
}